// round 1
// baseline (speedup 1.0000x reference)
#include <cuda_runtime.h>

// Problem constants
// B=8, H=W=128, DIM=512, NH=8, HD=64, WIN=8x8 (N=64 tokens/window), SHIFT=(4,4)
// windows: 8 * 16 * 16 = 2048 ; rows M = 2048*64 = 131072

#define NWIN 2048
#define NTOK 64
#define DIMC 512
#define NH_  8
#define HD_  64

// Scratch (device globals are the sanctioned scratch mechanism)
// g_qkv: [part(3)][win(2048)][head(8)][t(64)][d(64)]
__device__ float g_qkv[3u * 2048u * 8u * 64u * 64u];   // 805 MB
// g_o:   [m(131072)][h*64+d(512)]
__device__ float g_o[131072u * 512u];                  // 256 MB

// ---------------------------------------------------------------------------
// Kernel 1: QKV GEMM with fused roll+partition gather on A.
//   qkv[m,n] = sum_k xw[m,k] * qkv_w[n,k] + qkv_b[n]
//   M=131072 (gathered rows of x), K=512, N=1536
// Tile: BM=128, BN=128, BK=16, 256 threads, 8x8 per thread.
// ---------------------------------------------------------------------------
__global__ __launch_bounds__(256) void k_qkv_gemm(const float* __restrict__ x,
                                                  const float* __restrict__ W,
                                                  const float* __restrict__ bias)
{
    __shared__ float As[16 * 128];   // [k][m]
    __shared__ float Bs[16 * 128];   // [k][n]
    __shared__ int   rowOff[128];

    const int tid   = threadIdx.x;
    const int mTile = blockIdx.y;
    const int nTile = blockIdx.x;

    if (tid < 128) {
        int m   = mTile * 128 + tid;
        int win = m >> 6, t = m & 63;
        int b   = win >> 8;
        int wh  = (win >> 4) & 15;
        int ww  = win & 15;
        int i   = t >> 3, j = t & 7;
        int r   = (wh * 8 + i + 4) & 127;     // roll(-4) gather
        int c   = (ww * 8 + j + 4) & 127;
        rowOff[tid] = ((((b << 7) | r) << 7) | c) << 9;   // *512
    }
    __syncthreads();

    const int ty = tid >> 4;        // 0..15
    const int tx = tid & 15;        // 0..15
    const int n0 = nTile * 128;

    float acc[8][8];
#pragma unroll
    for (int i = 0; i < 8; i++)
#pragma unroll
        for (int j = 0; j < 8; j++) acc[i][j] = 0.f;

    for (int kt = 0; kt < 32; kt++) {
        const int k0 = kt * 16;
        // Load A tile (gathered), transposed into As[k][m]
#pragma unroll
        for (int it = 0; it < 2; it++) {
            int s   = tid + it * 256;       // 0..511
            int row = s >> 2;
            int k4  = (s & 3) * 4;
            float4 v = *(const float4*)(x + rowOff[row] + k0 + k4);
            As[(k4 + 0) * 128 + row] = v.x;
            As[(k4 + 1) * 128 + row] = v.y;
            As[(k4 + 2) * 128 + row] = v.z;
            As[(k4 + 3) * 128 + row] = v.w;
        }
        // Load B tile: Bs[k][n] = W[(n0+n)*512 + k0+k]
#pragma unroll
        for (int it = 0; it < 2; it++) {
            int s  = tid + it * 256;
            int n  = s >> 2;
            int k4 = (s & 3) * 4;
            float4 v = *(const float4*)(W + (size_t)(n0 + n) * 512 + k0 + k4);
            Bs[(k4 + 0) * 128 + n] = v.x;
            Bs[(k4 + 1) * 128 + n] = v.y;
            Bs[(k4 + 2) * 128 + n] = v.z;
            Bs[(k4 + 3) * 128 + n] = v.w;
        }
        __syncthreads();
#pragma unroll
        for (int k = 0; k < 16; k++) {
            float ra[8], rb[8];
#pragma unroll
            for (int i = 0; i < 8; i++) ra[i] = As[k * 128 + ty * 8 + i];
#pragma unroll
            for (int j = 0; j < 8; j++) rb[j] = Bs[k * 128 + tx * 8 + j];
#pragma unroll
            for (int i = 0; i < 8; i++)
#pragma unroll
                for (int j = 0; j < 8; j++) acc[i][j] += ra[i] * rb[j];
        }
        __syncthreads();
    }

    // Epilogue: add bias, scatter into g_qkv[part][win][h][t][d]
    const int nb   = n0 + tx * 8;           // 8-aligned -> same (part,h) block
    const int part = nb >> 9;
    const int rem  = nb & 511;
    const int h    = rem >> 6;
    const int d0   = rem & 63;
    float bv[8];
#pragma unroll
    for (int j = 0; j < 8; j++) bv[j] = bias[nb + j];

#pragma unroll
    for (int i = 0; i < 8; i++) {
        int m   = mTile * 128 + ty * 8 + i;
        int win = m >> 6, t = m & 63;
        size_t base = ((((size_t)part * 2048 + win) * 8 + h) * 64 + t) * 64 + d0;
#pragma unroll
        for (int j = 0; j < 8; j++)
            g_qkv[base + j] = acc[i][j] + bv[j];
    }
}

// ---------------------------------------------------------------------------
// Kernel 2: per (window, head) attention.
//   - loads q,k transposed [d][t] into smem, applies RoPE (+scale on q)
//   - S = q k^T  (64x64x64), mask (only windows with wh==15), softmax
//   - O = P V, scatter into g_o[m][h*64+d]
// Static smem: exactly 48 KB (3 * 64*64 fp32 buffers).
// ---------------------------------------------------------------------------
__global__ __launch_bounds__(256) void k_attn()
{
    __shared__ float qT[64 * 64];    // [d][t]; reused as V [t][d] later
    __shared__ float kT[64 * 64];    // [d][t]
    __shared__ float S [64 * 64];    // [r][c]

    const int tid = threadIdx.x;
    const int bid = blockIdx.x;          // 0..16383
    const int win = bid >> 3;
    const int h   = bid & 7;

    const size_t qbase = ((size_t)win * 8 + h) * 4096;
    const float* qg = g_qkv + qbase;
    const float* kg = g_qkv + (size_t)2048 * 8 * 4096 + qbase;
    const float* vg = g_qkv + (size_t)2 * 2048 * 8 * 4096 + qbase;

    // Load q,k transposed: smem[d][t] = g[t*64+d]
#pragma unroll
    for (int it = 0; it < 16; it++) {
        int e = tid + it * 256;          // 0..4095
        int t = e >> 6, d = e & 63;
        qT[d * 64 + t] = qg[e];
        kT[d * 64 + t] = kg[e];
    }
    __syncthreads();

    // RoPE: rotate pairs (db, db+16), db in [0,16) U [32,48).
    // pos = token-row (t/8) for first half, token-col (t%8) for second half.
    const float L2_10000 = 13.287712379549449f;   // log2(10000)
#pragma unroll
    for (int it = 0; it < 8; it++) {
        int p = tid + it * 256;          // 0..2047
        int t = p >> 5, q = p & 31;
        int db = (q < 16) ? q : (q + 16);
        int e  = db & 15;
        float pos = (db < 32) ? (float)(t >> 3) : (float)(t & 7);
        float inv = exp2f(-(float)e * (L2_10000 / 16.f));
        float ang = pos * inv;
        float cv = cosf(ang), sv = sinf(ang);

        float a = qT[db * 64 + t], b = qT[(db + 16) * 64 + t];
        qT[db * 64 + t]        = (a * cv - b * sv) * 0.125f;   // * SCALE
        qT[(db + 16) * 64 + t] = (b * cv + a * sv) * 0.125f;

        a = kT[db * 64 + t]; b = kT[(db + 16) * 64 + t];
        kT[db * 64 + t]        = a * cv - b * sv;
        kT[(db + 16) * 64 + t] = b * cv + a * sv;
    }
    __syncthreads();

    // S = q k^T : each thread computes a 4x4 block
    const int rr = (tid >> 4) << 2;      // 0..60
    const int cc = (tid & 15) << 2;      // 0..60
    {
        float acc[4][4] = {};
        for (int d = 0; d < 64; d++) {
            float qv[4], kv[4];
#pragma unroll
            for (int i = 0; i < 4; i++) qv[i] = qT[d * 64 + rr + i];
#pragma unroll
            for (int j = 0; j < 4; j++) kv[j] = kT[d * 64 + cc + j];
#pragma unroll
            for (int i = 0; i < 4; i++)
#pragma unroll
                for (int j = 0; j < 4; j++) acc[i][j] += qv[i] * kv[j];
        }
#pragma unroll
        for (int i = 0; i < 4; i++)
#pragma unroll
            for (int j = 0; j < 4; j++) S[(rr + i) * 64 + cc + j] = acc[i][j];
    }
    __syncthreads();

    // Load V into qT buffer (natural layout [t][d]); concurrently softmax rows.
#pragma unroll
    for (int it = 0; it < 16; it++) {
        int e = tid + it * 256;
        qT[e] = vg[e];
    }
    // Mask is degenerate (reference w_slices make region row-only):
    // only windows in the last row band (wh==15) are masked, with the
    // two halves (t<32 vs t>=32) mutually masked by -100.
    const bool maskOn = (((win >> 4) & 15) == 15);
    if (tid < 64) {
        int r = tid;
        float mx = -1e30f;
        for (int s = 0; s < 64; s++) {
            float v = S[r * 64 + s];
            if (maskOn && ((r < 32) != (s < 32))) v -= 100.f;
            S[r * 64 + s] = v;
            mx = fmaxf(mx, v);
        }
        float sum = 0.f;
        for (int s = 0; s < 64; s++) {
            float e2 = __expf(S[r * 64 + s] - mx);
            S[r * 64 + s] = e2;
            sum += e2;
        }
        float isum = 1.f / sum;
        for (int s = 0; s < 64; s++) S[r * 64 + s] *= isum;
    }
    __syncthreads();

    // O = P V
    {
        float o[4][4] = {};
        for (int s = 0; s < 64; s++) {
            float pv[4], vv[4];
#pragma unroll
            for (int i = 0; i < 4; i++) pv[i] = S[(rr + i) * 64 + s];
#pragma unroll
            for (int j = 0; j < 4; j++) vv[j] = qT[s * 64 + cc + j];
#pragma unroll
            for (int i = 0; i < 4; i++)
#pragma unroll
                for (int j = 0; j < 4; j++) o[i][j] += pv[i] * vv[j];
        }
#pragma unroll
        for (int i = 0; i < 4; i++) {
            size_t m = (size_t)win * 64 + rr + i;
            float4 val = make_float4(o[i][0], o[i][1], o[i][2], o[i][3]);
            *(float4*)(g_o + m * 512 + h * 64 + cc) = val;
        }
    }
}

// ---------------------------------------------------------------------------
// Kernel 3: proj GEMM + bias + fused unpartition/roll(+4) scatter.
//   out[m,n] = sum_k o[m,k] * proj_w[n,k] + proj_b[n]
//   M=131072, K=512, N=512
// ---------------------------------------------------------------------------
__global__ __launch_bounds__(256) void k_proj_gemm(const float* __restrict__ W,
                                                   const float* __restrict__ bias,
                                                   float* __restrict__ out)
{
    __shared__ float As[16 * 128];
    __shared__ float Bs[16 * 128];

    const int tid   = threadIdx.x;
    const int mTile = blockIdx.y;
    const int nTile = blockIdx.x;
    const int ty = tid >> 4;
    const int tx = tid & 15;
    const int n0 = nTile * 128;

    float acc[8][8];
#pragma unroll
    for (int i = 0; i < 8; i++)
#pragma unroll
        for (int j = 0; j < 8; j++) acc[i][j] = 0.f;

    for (int kt = 0; kt < 32; kt++) {
        const int k0 = kt * 16;
#pragma unroll
        for (int it = 0; it < 2; it++) {
            int s   = tid + it * 256;
            int row = s >> 2;
            int k4  = (s & 3) * 4;
            float4 v = *(const float4*)(g_o + (size_t)(mTile * 128 + row) * 512 + k0 + k4);
            As[(k4 + 0) * 128 + row] = v.x;
            As[(k4 + 1) * 128 + row] = v.y;
            As[(k4 + 2) * 128 + row] = v.z;
            As[(k4 + 3) * 128 + row] = v.w;
        }
#pragma unroll
        for (int it = 0; it < 2; it++) {
            int s  = tid + it * 256;
            int n  = s >> 2;
            int k4 = (s & 3) * 4;
            float4 v = *(const float4*)(W + (size_t)(n0 + n) * 512 + k0 + k4);
            Bs[(k4 + 0) * 128 + n] = v.x;
            Bs[(k4 + 1) * 128 + n] = v.y;
            Bs[(k4 + 2) * 128 + n] = v.z;
            Bs[(k4 + 3) * 128 + n] = v.w;
        }
        __syncthreads();
#pragma unroll
        for (int k = 0; k < 16; k++) {
            float ra[8], rb[8];
#pragma unroll
            for (int i = 0; i < 8; i++) ra[i] = As[k * 128 + ty * 8 + i];
#pragma unroll
            for (int j = 0; j < 8; j++) rb[j] = Bs[k * 128 + tx * 8 + j];
#pragma unroll
            for (int i = 0; i < 8; i++)
#pragma unroll
                for (int j = 0; j < 8; j++) acc[i][j] += ra[i] * rb[j];
        }
        __syncthreads();
    }

    const int nb = n0 + tx * 8;
    float bv[8];
#pragma unroll
    for (int j = 0; j < 8; j++) bv[j] = bias[nb + j];

#pragma unroll
    for (int i = 0; i < 8; i++) {
        int m   = mTile * 128 + ty * 8 + i;
        int win = m >> 6, t = m & 63;
        int b   = win >> 8;
        int wh  = (win >> 4) & 15;
        int ww  = win & 15;
        int ii  = t >> 3, jj = t & 7;
        int r   = (wh * 8 + ii + 4) & 127;    // unpartition + roll(+4) scatter
        int c   = (ww * 8 + jj + 4) & 127;
        size_t off = ((((size_t)b << 7) | r) << 7 | c) << 9;
#pragma unroll
        for (int j = 0; j < 8; j++)
            out[off + nb + j] = acc[i][j] + bv[j];
    }
}

// ---------------------------------------------------------------------------
extern "C" void kernel_launch(void* const* d_in, const int* in_sizes, int n_in,
                              void* d_out, int out_size)
{
    const float* x      = (const float*)d_in[0];
    const float* qkv_w  = (const float*)d_in[1];
    const float* qkv_b  = (const float*)d_in[2];
    const float* proj_w = (const float*)d_in[3];
    const float* proj_b = (const float*)d_in[4];
    float* out = (float*)d_out;

    // QKV: N=1536 -> 12 n-tiles, M=131072 -> 1024 m-tiles
    k_qkv_gemm<<<dim3(12, 1024), 256>>>(x, qkv_w, qkv_b);
    // Attention: one CTA per (window, head)
    k_attn<<<2048 * 8, 256>>>();
    // Proj: N=512 -> 4 n-tiles
    k_proj_gemm<<<dim3(4, 1024), 256>>>(proj_w, proj_b, out);
}

// round 2
// speedup vs baseline: 2.0448x; 2.0448x over previous
#include <cuda_runtime.h>
#include <cstdint>

// Problem constants:
// B=8, H=W=128, DIM=512, NH=8, HD=64, WIN=8x8 (N=64 tok/window), SHIFT=(4,4)
// windows: 2048 ; rows M = 131072

// Scratch (device globals = sanctioned scratch)
// g_qkv: [part(3)][win(2048)][head(8)][t(64)][d(64)]
__device__ float g_qkv[3u * 2048u * 8u * 64u * 64u];
// g_o:   [m(131072)][h*64+d(512)]
__device__ float g_o[131072u * 512u];

// ---------------------------------------------------------------------------
// helpers
// ---------------------------------------------------------------------------
__device__ __forceinline__ uint32_t f2tf32(float f) {
    uint32_t u;
    asm("cvt.rna.tf32.f32 %0, %1;" : "=r"(u) : "f"(f));
    return u;
}
__device__ __forceinline__ void cp16(uint32_t smem, const void* gmem) {
    asm volatile("cp.async.cg.shared.global [%0], [%1], 16;\n" :: "r"(smem), "l"(gmem));
}
__device__ __forceinline__ void mma_tf32(float* c, const uint32_t* a, const uint32_t* b) {
    asm volatile(
        "mma.sync.aligned.m16n8k8.row.col.f32.tf32.tf32.f32 "
        "{%0,%1,%2,%3}, {%4,%5,%6,%7}, {%8,%9}, {%0,%1,%2,%3};"
        : "+f"(c[0]), "+f"(c[1]), "+f"(c[2]), "+f"(c[3])
        : "r"(a[0]), "r"(a[1]), "r"(a[2]), "r"(a[3]), "r"(b[0]), "r"(b[1]));
}

#define SSTRIDE 36            // 32 floats + 4 pad -> conflict-free frag loads
#define STAGE_F (128 * SSTRIDE * 2)   // floats per stage (A + B)
#define SMEM_BYTES (2 * STAGE_F * 4)  // 73728

// ---------------------------------------------------------------------------
// Kernel 1: QKV GEMM (tf32 tensor cores) + fused roll+partition gather on A.
//   qkv[m,n] = sum_k xw[m,k]*qkv_w[n,k] + qkv_b[n];  M=131072 K=512 N=1536
// BM=BN=128, BK=32, 8 warps (4M x 2N), warp tile 32x64, mma m16n8k8.
// ---------------------------------------------------------------------------
__global__ __launch_bounds__(256, 2) void k_qkv_gemm(const float* __restrict__ x,
                                                     const float* __restrict__ W,
                                                     const float* __restrict__ bias)
{
    extern __shared__ float sm[];
    __shared__ int rowOff[128];

    const int tid   = threadIdx.x;
    const int nTile = blockIdx.x;       // fastest -> A tile L2 reuse across nTiles
    const int mTile = blockIdx.y;

    if (tid < 128) {
        int m   = mTile * 128 + tid;
        int win = m >> 6, t = m & 63;
        int b   = win >> 8;
        int wh  = (win >> 4) & 15;
        int ww  = win & 15;
        int i   = t >> 3, j = t & 7;
        int r   = (wh * 8 + i + 4) & 127;     // roll(-4) gather
        int c   = (ww * 8 + j + 4) & 127;
        rowOff[tid] = ((((b << 7) | r) << 7) | c) << 9;   // *512
    }
    __syncthreads();

    const int warpId = tid >> 5, lane = tid & 31;
    const int warpM  = warpId & 3;       // 0..3
    const int warpN  = warpId >> 2;      // 0..1
    const int n0     = nTile * 128;
    const int r      = lane >> 2, cq = lane & 3;

    float acc[2][8][4];
#pragma unroll
    for (int mi = 0; mi < 2; mi++)
#pragma unroll
        for (int ni = 0; ni < 8; ni++)
#pragma unroll
            for (int e = 0; e < 4; e++) acc[mi][ni][e] = 0.f;

    auto loadStage = [&](int stage, int k0) {
        float* As = sm + stage * STAGE_F;
        float* Bs = As + 128 * SSTRIDE;
#pragma unroll
        for (int it = 0; it < 4; it++) {
            int ch = tid + it * 256;          // 0..1023
            int row = ch >> 3, ci = ch & 7;   // 16B chunk index
            uint32_t sa = (uint32_t)__cvta_generic_to_shared(As + row * SSTRIDE + ci * 4);
            cp16(sa, x + rowOff[row] + k0 + ci * 4);
            uint32_t sb = (uint32_t)__cvta_generic_to_shared(Bs + row * SSTRIDE + ci * 4);
            cp16(sb, W + (size_t)(n0 + row) * 512 + k0 + ci * 4);
        }
    };

    loadStage(0, 0);
    asm volatile("cp.async.commit_group;\n");

    for (int kt = 0; kt < 16; kt++) {
        if (kt < 15) {
            loadStage((kt + 1) & 1, (kt + 1) * 32);
            asm volatile("cp.async.commit_group;\n");
            asm volatile("cp.async.wait_group 1;\n");
        } else {
            asm volatile("cp.async.wait_group 0;\n");
        }
        __syncthreads();

        const float* As = sm + (kt & 1) * STAGE_F;
        const float* Bs = As + 128 * SSTRIDE;
#pragma unroll
        for (int ks = 0; ks < 4; ks++) {
            uint32_t af[2][4];
#pragma unroll
            for (int mi = 0; mi < 2; mi++) {
                const float* ap = As + (warpM * 32 + mi * 16 + r) * SSTRIDE + ks * 8 + cq;
                af[mi][0] = f2tf32(ap[0]);
                af[mi][1] = f2tf32(ap[8 * SSTRIDE]);
                af[mi][2] = f2tf32(ap[4]);
                af[mi][3] = f2tf32(ap[8 * SSTRIDE + 4]);
            }
#pragma unroll
            for (int ni = 0; ni < 8; ni++) {
                const float* bp = Bs + (warpN * 64 + ni * 8 + r) * SSTRIDE + ks * 8 + cq;
                uint32_t bf[2];
                bf[0] = f2tf32(bp[0]);
                bf[1] = f2tf32(bp[4]);
                mma_tf32(acc[0][ni], af[0], bf);
                mma_tf32(acc[1][ni], af[1], bf);
            }
        }
        __syncthreads();
    }

    // Epilogue: bias + scatter into g_qkv[part][win][h][t][d]
#pragma unroll
    for (int ni = 0; ni < 8; ni++) {
        int n  = n0 + warpN * 64 + ni * 8 + 2 * cq;
        float b0 = bias[n], b1 = bias[n + 1];
        int part = n >> 9;
        int h    = (n >> 6) & 7;
        int d0   = n & 63;
#pragma unroll
        for (int mi = 0; mi < 2; mi++) {
#pragma unroll
            for (int rr = 0; rr < 2; rr++) {
                int m   = mTile * 128 + warpM * 32 + mi * 16 + r + rr * 8;
                int win = m >> 6, t = m & 63;
                size_t idx = ((((size_t)part * 2048 + win) * 8 + h) * 64 + t) * 64 + d0;
                float2 v = make_float2(acc[mi][ni][rr * 2 + 0] + b0,
                                       acc[mi][ni][rr * 2 + 1] + b1);
                *(float2*)(g_qkv + idx) = v;
            }
        }
    }
}

// ---------------------------------------------------------------------------
// Kernel 2: per (window, head) attention (unchanged from R1, fp32).
// ---------------------------------------------------------------------------
__global__ __launch_bounds__(256) void k_attn()
{
    __shared__ float qT[64 * 64];    // [d][t]; reused as V [t][d] later
    __shared__ float kT[64 * 64];    // [d][t]
    __shared__ float S [64 * 64];    // [r][c]

    const int tid = threadIdx.x;
    const int bid = blockIdx.x;
    const int win = bid >> 3;
    const int h   = bid & 7;

    const size_t qbase = ((size_t)win * 8 + h) * 4096;
    const float* qg = g_qkv + qbase;
    const float* kg = g_qkv + (size_t)2048 * 8 * 4096 + qbase;
    const float* vg = g_qkv + (size_t)2 * 2048 * 8 * 4096 + qbase;

#pragma unroll
    for (int it = 0; it < 16; it++) {
        int e = tid + it * 256;
        int t = e >> 6, d = e & 63;
        qT[d * 64 + t] = qg[e];
        kT[d * 64 + t] = kg[e];
    }
    __syncthreads();

    const float L2_10000 = 13.287712379549449f;
#pragma unroll
    for (int it = 0; it < 8; it++) {
        int p = tid + it * 256;
        int t = p >> 5, q = p & 31;
        int db = (q < 16) ? q : (q + 16);
        int e  = db & 15;
        float pos = (db < 32) ? (float)(t >> 3) : (float)(t & 7);
        float inv = exp2f(-(float)e * (L2_10000 / 16.f));
        float ang = pos * inv;
        float cv = cosf(ang), sv = sinf(ang);

        float a = qT[db * 64 + t], b = qT[(db + 16) * 64 + t];
        qT[db * 64 + t]        = (a * cv - b * sv) * 0.125f;
        qT[(db + 16) * 64 + t] = (b * cv + a * sv) * 0.125f;

        a = kT[db * 64 + t]; b = kT[(db + 16) * 64 + t];
        kT[db * 64 + t]        = a * cv - b * sv;
        kT[(db + 16) * 64 + t] = b * cv + a * sv;
    }
    __syncthreads();

    const int rr = (tid >> 4) << 2;
    const int cc = (tid & 15) << 2;
    {
        float acc[4][4] = {};
        for (int d = 0; d < 64; d++) {
            float qv[4], kv[4];
#pragma unroll
            for (int i = 0; i < 4; i++) qv[i] = qT[d * 64 + rr + i];
#pragma unroll
            for (int j = 0; j < 4; j++) kv[j] = kT[d * 64 + cc + j];
#pragma unroll
            for (int i = 0; i < 4; i++)
#pragma unroll
                for (int j = 0; j < 4; j++) acc[i][j] += qv[i] * kv[j];
        }
#pragma unroll
        for (int i = 0; i < 4; i++)
#pragma unroll
            for (int j = 0; j < 4; j++) S[(rr + i) * 64 + cc + j] = acc[i][j];
    }
    __syncthreads();

#pragma unroll
    for (int it = 0; it < 16; it++) {
        int e = tid + it * 256;
        qT[e] = vg[e];
    }
    const bool maskOn = (((win >> 4) & 15) == 15);
    if (tid < 64) {
        int r = tid;
        float mx = -1e30f;
        for (int s = 0; s < 64; s++) {
            float v = S[r * 64 + s];
            if (maskOn && ((r < 32) != (s < 32))) v -= 100.f;
            S[r * 64 + s] = v;
            mx = fmaxf(mx, v);
        }
        float sum = 0.f;
        for (int s = 0; s < 64; s++) {
            float e2 = __expf(S[r * 64 + s] - mx);
            S[r * 64 + s] = e2;
            sum += e2;
        }
        float isum = 1.f / sum;
        for (int s = 0; s < 64; s++) S[r * 64 + s] *= isum;
    }
    __syncthreads();

    {
        float o[4][4] = {};
        for (int s = 0; s < 64; s++) {
            float pv[4], vv[4];
#pragma unroll
            for (int i = 0; i < 4; i++) pv[i] = S[(rr + i) * 64 + s];
#pragma unroll
            for (int j = 0; j < 4; j++) vv[j] = qT[s * 64 + cc + j];
#pragma unroll
            for (int i = 0; i < 4; i++)
#pragma unroll
                for (int j = 0; j < 4; j++) o[i][j] += pv[i] * vv[j];
        }
#pragma unroll
        for (int i = 0; i < 4; i++) {
            size_t m = (size_t)win * 64 + rr + i;
            float4 val = make_float4(o[i][0], o[i][1], o[i][2], o[i][3]);
            *(float4*)(g_o + m * 512 + h * 64 + cc) = val;
        }
    }
}

// ---------------------------------------------------------------------------
// Kernel 3: proj GEMM (tf32 tensor cores) + bias + unpartition/roll scatter.
//   out[m,n] = sum_k o[m,k]*proj_w[n,k] + proj_b[n];  M=131072 K=512 N=512
// ---------------------------------------------------------------------------
__global__ __launch_bounds__(256, 2) void k_proj_gemm(const float* __restrict__ W,
                                                      const float* __restrict__ bias,
                                                      float* __restrict__ out)
{
    extern __shared__ float sm[];

    const int tid   = threadIdx.x;
    const int nTile = blockIdx.x;
    const int mTile = blockIdx.y;

    const int warpId = tid >> 5, lane = tid & 31;
    const int warpM  = warpId & 3;
    const int warpN  = warpId >> 2;
    const int n0     = nTile * 128;
    const int r      = lane >> 2, cq = lane & 3;

    float acc[2][8][4];
#pragma unroll
    for (int mi = 0; mi < 2; mi++)
#pragma unroll
        for (int ni = 0; ni < 8; ni++)
#pragma unroll
            for (int e = 0; e < 4; e++) acc[mi][ni][e] = 0.f;

    auto loadStage = [&](int stage, int k0) {
        float* As = sm + stage * STAGE_F;
        float* Bs = As + 128 * SSTRIDE;
#pragma unroll
        for (int it = 0; it < 4; it++) {
            int ch = tid + it * 256;
            int row = ch >> 3, ci = ch & 7;
            uint32_t sa = (uint32_t)__cvta_generic_to_shared(As + row * SSTRIDE + ci * 4);
            cp16(sa, g_o + (size_t)(mTile * 128 + row) * 512 + k0 + ci * 4);
            uint32_t sb = (uint32_t)__cvta_generic_to_shared(Bs + row * SSTRIDE + ci * 4);
            cp16(sb, W + (size_t)(n0 + row) * 512 + k0 + ci * 4);
        }
    };

    loadStage(0, 0);
    asm volatile("cp.async.commit_group;\n");

    for (int kt = 0; kt < 16; kt++) {
        if (kt < 15) {
            loadStage((kt + 1) & 1, (kt + 1) * 32);
            asm volatile("cp.async.commit_group;\n");
            asm volatile("cp.async.wait_group 1;\n");
        } else {
            asm volatile("cp.async.wait_group 0;\n");
        }
        __syncthreads();

        const float* As = sm + (kt & 1) * STAGE_F;
        const float* Bs = As + 128 * SSTRIDE;
#pragma unroll
        for (int ks = 0; ks < 4; ks++) {
            uint32_t af[2][4];
#pragma unroll
            for (int mi = 0; mi < 2; mi++) {
                const float* ap = As + (warpM * 32 + mi * 16 + r) * SSTRIDE + ks * 8 + cq;
                af[mi][0] = f2tf32(ap[0]);
                af[mi][1] = f2tf32(ap[8 * SSTRIDE]);
                af[mi][2] = f2tf32(ap[4]);
                af[mi][3] = f2tf32(ap[8 * SSTRIDE + 4]);
            }
#pragma unroll
            for (int ni = 0; ni < 8; ni++) {
                const float* bp = Bs + (warpN * 64 + ni * 8 + r) * SSTRIDE + ks * 8 + cq;
                uint32_t bf[2];
                bf[0] = f2tf32(bp[0]);
                bf[1] = f2tf32(bp[4]);
                mma_tf32(acc[0][ni], af[0], bf);
                mma_tf32(acc[1][ni], af[1], bf);
            }
        }
        __syncthreads();
    }

    // Epilogue: bias + unpartition/roll(+4) scatter
#pragma unroll
    for (int ni = 0; ni < 8; ni++) {
        int n  = n0 + warpN * 64 + ni * 8 + 2 * cq;
        float b0 = bias[n], b1 = bias[n + 1];
#pragma unroll
        for (int mi = 0; mi < 2; mi++) {
#pragma unroll
            for (int rr2 = 0; rr2 < 2; rr2++) {
                int m   = mTile * 128 + warpM * 32 + mi * 16 + r + rr2 * 8;
                int win = m >> 6, t = m & 63;
                int b   = win >> 8;
                int wh  = (win >> 4) & 15;
                int ww  = win & 15;
                int ii  = t >> 3, jj = t & 7;
                int rO  = (wh * 8 + ii + 4) & 127;
                int cO  = (ww * 8 + jj + 4) & 127;
                size_t off = ((((size_t)b << 7) | rO) << 7 | cO) << 9;
                float2 v = make_float2(acc[mi][ni][rr2 * 2 + 0] + b0,
                                       acc[mi][ni][rr2 * 2 + 1] + b1);
                *(float2*)(out + off + n) = v;
            }
        }
    }
}

// ---------------------------------------------------------------------------
extern "C" void kernel_launch(void* const* d_in, const int* in_sizes, int n_in,
                              void* d_out, int out_size)
{
    const float* x      = (const float*)d_in[0];
    const float* qkv_w  = (const float*)d_in[1];
    const float* qkv_b  = (const float*)d_in[2];
    const float* proj_w = (const float*)d_in[3];
    const float* proj_b = (const float*)d_in[4];
    float* out = (float*)d_out;

    cudaFuncSetAttribute(k_qkv_gemm,  cudaFuncAttributeMaxDynamicSharedMemorySize, SMEM_BYTES);
    cudaFuncSetAttribute(k_proj_gemm, cudaFuncAttributeMaxDynamicSharedMemorySize, SMEM_BYTES);

    k_qkv_gemm<<<dim3(12, 1024), 256, SMEM_BYTES>>>(x, qkv_w, qkv_b);
    k_attn<<<2048 * 8, 256>>>();
    k_proj_gemm<<<dim3(4, 1024), 256, SMEM_BYTES>>>(proj_w, proj_b, out);
}

// round 3
// speedup vs baseline: 4.6175x; 2.2581x over previous
#include <cuda_runtime.h>
#include <cstdint>

// Problem constants:
// B=8, H=W=128, DIM=512, NH=8, HD=64, WIN=8x8 (N=64 tok/window), SHIFT=(4,4)
// windows: 2048 ; rows M = 131072

// Scratch (device globals = sanctioned scratch)
// g_qkv: [part(3)][win(2048)][head(8)][t(64)][d(64)]
__device__ float g_qkv[3u * 2048u * 8u * 64u * 64u];
// g_o:   [m(131072)][h*64+d(512)]
__device__ float g_o[131072u * 512u];

// ---------------------------------------------------------------------------
// helpers
// ---------------------------------------------------------------------------
__device__ __forceinline__ uint32_t f2tf32(float f) {
    uint32_t u;
    asm("cvt.rna.tf32.f32 %0, %1;" : "=r"(u) : "f"(f));
    return u;
}
__device__ __forceinline__ void cp16(uint32_t smem, const void* gmem) {
    asm volatile("cp.async.cg.shared.global [%0], [%1], 16;\n" :: "r"(smem), "l"(gmem));
}
__device__ __forceinline__ void mma_tf32(float* c, const uint32_t* a, const uint32_t* b) {
    asm volatile(
        "mma.sync.aligned.m16n8k8.row.col.f32.tf32.tf32.f32 "
        "{%0,%1,%2,%3}, {%4,%5,%6,%7}, {%8,%9}, {%0,%1,%2,%3};"
        : "+f"(c[0]), "+f"(c[1]), "+f"(c[2]), "+f"(c[3])
        : "r"(a[0]), "r"(a[1]), "r"(a[2]), "r"(a[3]), "r"(b[0]), "r"(b[1]));
}

#define SSTRIDE 36            // 32 floats + 4 pad -> conflict-free frag loads
#define STAGE_F (128 * SSTRIDE * 2)   // floats per stage (A + B)
#define SMEM_BYTES (2 * STAGE_F * 4)  // 73728

// ---------------------------------------------------------------------------
// Kernel 1: QKV GEMM (tf32 tensor cores) + fused roll+partition gather on A.
//   qkv[m,n] = sum_k xw[m,k]*qkv_w[n,k] + qkv_b[n];  M=131072 K=512 N=1536
// ---------------------------------------------------------------------------
__global__ __launch_bounds__(256, 2) void k_qkv_gemm(const float* __restrict__ x,
                                                     const float* __restrict__ W,
                                                     const float* __restrict__ bias)
{
    extern __shared__ float sm[];
    __shared__ int rowOff[128];

    const int tid   = threadIdx.x;
    const int nTile = blockIdx.x;
    const int mTile = blockIdx.y;

    if (tid < 128) {
        int m   = mTile * 128 + tid;
        int win = m >> 6, t = m & 63;
        int b   = win >> 8;
        int wh  = (win >> 4) & 15;
        int ww  = win & 15;
        int i   = t >> 3, j = t & 7;
        int r   = (wh * 8 + i + 4) & 127;
        int c   = (ww * 8 + j + 4) & 127;
        rowOff[tid] = ((((b << 7) | r) << 7) | c) << 9;
    }
    __syncthreads();

    const int warpId = tid >> 5, lane = tid & 31;
    const int warpM  = warpId & 3;
    const int warpN  = warpId >> 2;
    const int n0     = nTile * 128;
    const int r      = lane >> 2, cq = lane & 3;

    float acc[2][8][4];
#pragma unroll
    for (int mi = 0; mi < 2; mi++)
#pragma unroll
        for (int ni = 0; ni < 8; ni++)
#pragma unroll
            for (int e = 0; e < 4; e++) acc[mi][ni][e] = 0.f;

    auto loadStage = [&](int stage, int k0) {
        float* As = sm + stage * STAGE_F;
        float* Bs = As + 128 * SSTRIDE;
#pragma unroll
        for (int it = 0; it < 4; it++) {
            int ch = tid + it * 256;
            int row = ch >> 3, ci = ch & 7;
            uint32_t sa = (uint32_t)__cvta_generic_to_shared(As + row * SSTRIDE + ci * 4);
            cp16(sa, x + rowOff[row] + k0 + ci * 4);
            uint32_t sb = (uint32_t)__cvta_generic_to_shared(Bs + row * SSTRIDE + ci * 4);
            cp16(sb, W + (size_t)(n0 + row) * 512 + k0 + ci * 4);
        }
    };

    loadStage(0, 0);
    asm volatile("cp.async.commit_group;\n");

    for (int kt = 0; kt < 16; kt++) {
        if (kt < 15) {
            loadStage((kt + 1) & 1, (kt + 1) * 32);
            asm volatile("cp.async.commit_group;\n");
            asm volatile("cp.async.wait_group 1;\n");
        } else {
            asm volatile("cp.async.wait_group 0;\n");
        }
        __syncthreads();

        const float* As = sm + (kt & 1) * STAGE_F;
        const float* Bs = As + 128 * SSTRIDE;
#pragma unroll
        for (int ks = 0; ks < 4; ks++) {
            uint32_t af[2][4];
#pragma unroll
            for (int mi = 0; mi < 2; mi++) {
                const float* ap = As + (warpM * 32 + mi * 16 + r) * SSTRIDE + ks * 8 + cq;
                af[mi][0] = f2tf32(ap[0]);
                af[mi][1] = f2tf32(ap[8 * SSTRIDE]);
                af[mi][2] = f2tf32(ap[4]);
                af[mi][3] = f2tf32(ap[8 * SSTRIDE + 4]);
            }
#pragma unroll
            for (int ni = 0; ni < 8; ni++) {
                const float* bp = Bs + (warpN * 64 + ni * 8 + r) * SSTRIDE + ks * 8 + cq;
                uint32_t bf[2];
                bf[0] = f2tf32(bp[0]);
                bf[1] = f2tf32(bp[4]);
                mma_tf32(acc[0][ni], af[0], bf);
                mma_tf32(acc[1][ni], af[1], bf);
            }
        }
        __syncthreads();
    }

#pragma unroll
    for (int ni = 0; ni < 8; ni++) {
        int n  = n0 + warpN * 64 + ni * 8 + 2 * cq;
        float b0 = bias[n], b1 = bias[n + 1];
        int part = n >> 9;
        int h    = (n >> 6) & 7;
        int d0   = n & 63;
#pragma unroll
        for (int mi = 0; mi < 2; mi++) {
#pragma unroll
            for (int rr = 0; rr < 2; rr++) {
                int m   = mTile * 128 + warpM * 32 + mi * 16 + r + rr * 8;
                int win = m >> 6, t = m & 63;
                size_t idx = ((((size_t)part * 2048 + win) * 8 + h) * 64 + t) * 64 + d0;
                float2 v = make_float2(acc[mi][ni][rr * 2 + 0] + b0,
                                       acc[mi][ni][rr * 2 + 1] + b1);
                *(float2*)(g_qkv + idx) = v;
            }
        }
    }
}

// ---------------------------------------------------------------------------
// Kernel 2: per (window, head) attention on tensor cores (tf32 mma).
// 128 threads = 4 warps; warp w owns S/O rows [16w, 16w+16).
// smem: Qb (Q, later P), Kb (K, later V); stride 68 floats (bank = 4r+c).
// ---------------------------------------------------------------------------
#define AST 68   // attention smem row stride (floats)

__global__ __launch_bounds__(128) void k_attn_mma()
{
    __shared__ float Qb[64 * AST];   // Q -> P
    __shared__ float Kb[64 * AST];   // K -> V

    const int tid  = threadIdx.x;
    const int warp = tid >> 5;
    const int lane = tid & 31;
    const int r    = lane >> 2;      // 0..7
    const int c    = lane & 3;       // 0..3
    const int m0   = warp * 16;

    const int win = blockIdx.x >> 3;
    const int h   = blockIdx.x & 7;

    const size_t qbase = ((size_t)win * 8 + h) * 4096;
    const float4* qg = (const float4*)(g_qkv + qbase);
    const float4* kg = (const float4*)(g_qkv + (size_t)2048 * 8 * 4096 + qbase);
    const float4* vg = (const float4*)(g_qkv + (size_t)2 * 2048 * 8 * 4096 + qbase);

    // Load Q, K ([t][d] natural, padded stride)
#pragma unroll
    for (int it = 0; it < 8; it++) {
        int e4 = tid + it * 128;          // 0..1023
        int t  = e4 >> 4;
        int d4 = (e4 & 15) * 4;
        *(float4*)(Qb + t * AST + d4) = qg[e4];
        *(float4*)(Kb + t * AST + d4) = kg[e4];
    }
    __syncthreads();

    // RoPE (pairs (db, db+16), db in [0,16) U [32,48)); scale Q by 0.125.
    const float L2_10000 = 13.287712379549449f;
#pragma unroll
    for (int it = 0; it < 16; it++) {
        int p = tid + it * 128;           // 0..2047
        int t = p >> 5, q = p & 31;
        int db = (q < 16) ? q : (q + 16);
        int e  = db & 15;
        float pos = (db < 32) ? (float)(t >> 3) : (float)(t & 7);
        float inv = exp2f(-(float)e * (L2_10000 / 16.f));
        float ang = pos * inv;
        float cv = cosf(ang), sv = sinf(ang);

        float a = Qb[t * AST + db], b = Qb[t * AST + db + 16];
        Qb[t * AST + db]      = (a * cv - b * sv) * 0.125f;
        Qb[t * AST + db + 16] = (b * cv + a * sv) * 0.125f;

        a = Kb[t * AST + db]; b = Kb[t * AST + db + 16];
        Kb[t * AST + db]      = a * cv - b * sv;
        Kb[t * AST + db + 16] = b * cv + a * sv;
    }
    __syncthreads();

    // ---- S = Q K^T (warp strip 16x64) ----
    uint32_t areg[8][4];
#pragma unroll
    for (int ks = 0; ks < 8; ks++) {
        const float* ap = Qb + (m0 + r) * AST + ks * 8 + c;
        areg[ks][0] = f2tf32(ap[0]);
        areg[ks][1] = f2tf32(ap[8 * AST]);
        areg[ks][2] = f2tf32(ap[4]);
        areg[ks][3] = f2tf32(ap[8 * AST + 4]);
    }

    float sacc[8][4];
#pragma unroll
    for (int ni = 0; ni < 8; ni++)
#pragma unroll
        for (int e = 0; e < 4; e++) sacc[ni][e] = 0.f;

#pragma unroll
    for (int ni = 0; ni < 8; ni++) {
        const float* bbase = Kb + (ni * 8 + r) * AST + c;
#pragma unroll
        for (int ks = 0; ks < 8; ks++) {
            uint32_t bf[2];
            bf[0] = f2tf32(bbase[ks * 8]);
            bf[1] = f2tf32(bbase[ks * 8 + 4]);
            mma_tf32(sacc[ni], areg[ks], bf);
        }
    }
    __syncthreads();   // all warps done reading Kb -> safe to overwrite with V

    // ---- V load into Kb (overlaps softmax register work below it) ----
#pragma unroll
    for (int it = 0; it < 8; it++) {
        int e4 = tid + it * 128;
        int t  = e4 >> 4;
        int d4 = (e4 & 15) * 4;
        *(float4*)(Kb + t * AST + d4) = vg[e4];
    }

    // ---- mask + softmax, fully in registers ----
    // mask degenerate: only windows with wh==15; -100 iff (row<32) != (col<32).
    // row<32 <=> warp<2 (both rows of the fragment); col<32 <=> ni<4.
    const bool maskOn = (((win >> 4) & 15) == 15);
    const bool warpLo = (warp < 2);

    float mx1 = -1e30f, mx2 = -1e30f;
#pragma unroll
    for (int ni = 0; ni < 8; ni++) {
        float msub = (maskOn && ((ni < 4) != warpLo)) ? 100.f : 0.f;
        sacc[ni][0] -= msub; sacc[ni][1] -= msub;
        sacc[ni][2] -= msub; sacc[ni][3] -= msub;
        mx1 = fmaxf(mx1, fmaxf(sacc[ni][0], sacc[ni][1]));
        mx2 = fmaxf(mx2, fmaxf(sacc[ni][2], sacc[ni][3]));
    }
    mx1 = fmaxf(mx1, __shfl_xor_sync(0xffffffffu, mx1, 1));
    mx1 = fmaxf(mx1, __shfl_xor_sync(0xffffffffu, mx1, 2));
    mx2 = fmaxf(mx2, __shfl_xor_sync(0xffffffffu, mx2, 1));
    mx2 = fmaxf(mx2, __shfl_xor_sync(0xffffffffu, mx2, 2));

    float s1 = 0.f, s2 = 0.f;
#pragma unroll
    for (int ni = 0; ni < 8; ni++) {
        sacc[ni][0] = __expf(sacc[ni][0] - mx1);
        sacc[ni][1] = __expf(sacc[ni][1] - mx1);
        sacc[ni][2] = __expf(sacc[ni][2] - mx2);
        sacc[ni][3] = __expf(sacc[ni][3] - mx2);
        s1 += sacc[ni][0] + sacc[ni][1];
        s2 += sacc[ni][2] + sacc[ni][3];
    }
    s1 += __shfl_xor_sync(0xffffffffu, s1, 1);
    s1 += __shfl_xor_sync(0xffffffffu, s1, 2);
    s2 += __shfl_xor_sync(0xffffffffu, s2, 1);
    s2 += __shfl_xor_sync(0xffffffffu, s2, 2);
    const float i1 = 1.f / s1, i2 = 1.f / s2;

    // store P into own 16-row strip of Qb (C-layout -> A-layout restage)
#pragma unroll
    for (int ni = 0; ni < 8; ni++) {
        *(float2*)(Qb + (m0 + r) * AST + ni * 8 + 2 * c) =
            make_float2(sacc[ni][0] * i1, sacc[ni][1] * i1);
        *(float2*)(Qb + (m0 + r + 8) * AST + ni * 8 + 2 * c) =
            make_float2(sacc[ni][2] * i2, sacc[ni][3] * i2);
    }
    __syncthreads();   // V fully in Kb; own-strip P visible (per-warp anyway)

    // ---- O = P V ----
    uint32_t preg[8][4];
#pragma unroll
    for (int ks = 0; ks < 8; ks++) {
        const float* pp = Qb + (m0 + r) * AST + ks * 8 + c;
        preg[ks][0] = f2tf32(pp[0]);
        preg[ks][1] = f2tf32(pp[8 * AST]);
        preg[ks][2] = f2tf32(pp[4]);
        preg[ks][3] = f2tf32(pp[8 * AST + 4]);
    }

    float oacc[8][4];
#pragma unroll
    for (int ni = 0; ni < 8; ni++)
#pragma unroll
        for (int e = 0; e < 4; e++) oacc[ni][e] = 0.f;

#pragma unroll
    for (int ni = 0; ni < 8; ni++) {
        const float* vb = Kb + c * AST + ni * 8 + r;
#pragma unroll
        for (int ks = 0; ks < 8; ks++) {
            uint32_t bf[2];
            bf[0] = f2tf32(vb[ks * 8 * AST]);
            bf[1] = f2tf32(vb[(ks * 8 + 4) * AST]);
            mma_tf32(oacc[ni], preg[ks], bf);
        }
    }

    // write O to g_o[m][h*64+d]
    const size_t mrow1 = (size_t)win * 64 + m0 + r;
    const size_t mrow2 = mrow1 + 8;
#pragma unroll
    for (int ni = 0; ni < 8; ni++) {
        int d0 = h * 64 + ni * 8 + 2 * c;
        *(float2*)(g_o + mrow1 * 512 + d0) = make_float2(oacc[ni][0], oacc[ni][1]);
        *(float2*)(g_o + mrow2 * 512 + d0) = make_float2(oacc[ni][2], oacc[ni][3]);
    }
}

// ---------------------------------------------------------------------------
// Kernel 3: proj GEMM (tf32) + bias + unpartition/roll scatter.
//   out[m,n] = sum_k o[m,k]*proj_w[n,k] + proj_b[n];  M=131072 K=512 N=512
// ---------------------------------------------------------------------------
__global__ __launch_bounds__(256, 2) void k_proj_gemm(const float* __restrict__ W,
                                                      const float* __restrict__ bias,
                                                      float* __restrict__ out)
{
    extern __shared__ float sm[];

    const int tid   = threadIdx.x;
    const int nTile = blockIdx.x;
    const int mTile = blockIdx.y;

    const int warpId = tid >> 5, lane = tid & 31;
    const int warpM  = warpId & 3;
    const int warpN  = warpId >> 2;
    const int n0     = nTile * 128;
    const int r      = lane >> 2, cq = lane & 3;

    float acc[2][8][4];
#pragma unroll
    for (int mi = 0; mi < 2; mi++)
#pragma unroll
        for (int ni = 0; ni < 8; ni++)
#pragma unroll
            for (int e = 0; e < 4; e++) acc[mi][ni][e] = 0.f;

    auto loadStage = [&](int stage, int k0) {
        float* As = sm + stage * STAGE_F;
        float* Bs = As + 128 * SSTRIDE;
#pragma unroll
        for (int it = 0; it < 4; it++) {
            int ch = tid + it * 256;
            int row = ch >> 3, ci = ch & 7;
            uint32_t sa = (uint32_t)__cvta_generic_to_shared(As + row * SSTRIDE + ci * 4);
            cp16(sa, g_o + (size_t)(mTile * 128 + row) * 512 + k0 + ci * 4);
            uint32_t sb = (uint32_t)__cvta_generic_to_shared(Bs + row * SSTRIDE + ci * 4);
            cp16(sb, W + (size_t)(n0 + row) * 512 + k0 + ci * 4);
        }
    };

    loadStage(0, 0);
    asm volatile("cp.async.commit_group;\n");

    for (int kt = 0; kt < 16; kt++) {
        if (kt < 15) {
            loadStage((kt + 1) & 1, (kt + 1) * 32);
            asm volatile("cp.async.commit_group;\n");
            asm volatile("cp.async.wait_group 1;\n");
        } else {
            asm volatile("cp.async.wait_group 0;\n");
        }
        __syncthreads();

        const float* As = sm + (kt & 1) * STAGE_F;
        const float* Bs = As + 128 * SSTRIDE;
#pragma unroll
        for (int ks = 0; ks < 4; ks++) {
            uint32_t af[2][4];
#pragma unroll
            for (int mi = 0; mi < 2; mi++) {
                const float* ap = As + (warpM * 32 + mi * 16 + r) * SSTRIDE + ks * 8 + cq;
                af[mi][0] = f2tf32(ap[0]);
                af[mi][1] = f2tf32(ap[8 * SSTRIDE]);
                af[mi][2] = f2tf32(ap[4]);
                af[mi][3] = f2tf32(ap[8 * SSTRIDE + 4]);
            }
#pragma unroll
            for (int ni = 0; ni < 8; ni++) {
                const float* bp = Bs + (warpN * 64 + ni * 8 + r) * SSTRIDE + ks * 8 + cq;
                uint32_t bf[2];
                bf[0] = f2tf32(bp[0]);
                bf[1] = f2tf32(bp[4]);
                mma_tf32(acc[0][ni], af[0], bf);
                mma_tf32(acc[1][ni], af[1], bf);
            }
        }
        __syncthreads();
    }

#pragma unroll
    for (int ni = 0; ni < 8; ni++) {
        int n  = n0 + warpN * 64 + ni * 8 + 2 * cq;
        float b0 = bias[n], b1 = bias[n + 1];
#pragma unroll
        for (int mi = 0; mi < 2; mi++) {
#pragma unroll
            for (int rr2 = 0; rr2 < 2; rr2++) {
                int m   = mTile * 128 + warpM * 32 + mi * 16 + r + rr2 * 8;
                int win = m >> 6, t = m & 63;
                int b   = win >> 8;
                int wh  = (win >> 4) & 15;
                int ww  = win & 15;
                int ii  = t >> 3, jj = t & 7;
                int rO  = (wh * 8 + ii + 4) & 127;
                int cO  = (ww * 8 + jj + 4) & 127;
                size_t off = ((((size_t)b << 7) | rO) << 7 | cO) << 9;
                float2 v = make_float2(acc[mi][ni][rr2 * 2 + 0] + b0,
                                       acc[mi][ni][rr2 * 2 + 1] + b1);
                *(float2*)(out + off + n) = v;
            }
        }
    }
}

// ---------------------------------------------------------------------------
extern "C" void kernel_launch(void* const* d_in, const int* in_sizes, int n_in,
                              void* d_out, int out_size)
{
    const float* x      = (const float*)d_in[0];
    const float* qkv_w  = (const float*)d_in[1];
    const float* qkv_b  = (const float*)d_in[2];
    const float* proj_w = (const float*)d_in[3];
    const float* proj_b = (const float*)d_in[4];
    float* out = (float*)d_out;

    cudaFuncSetAttribute(k_qkv_gemm,  cudaFuncAttributeMaxDynamicSharedMemorySize, SMEM_BYTES);
    cudaFuncSetAttribute(k_proj_gemm, cudaFuncAttributeMaxDynamicSharedMemorySize, SMEM_BYTES);

    k_qkv_gemm<<<dim3(12, 1024), 256, SMEM_BYTES>>>(x, qkv_w, qkv_b);
    k_attn_mma<<<2048 * 8, 128>>>();
    k_proj_gemm<<<dim3(4, 1024), 256, SMEM_BYTES>>>(proj_w, proj_b, out);
}

// round 4
// speedup vs baseline: 4.6766x; 1.0128x over previous
#include <cuda_runtime.h>
#include <cstdint>

// Problem constants:
// B=8, H=W=128, DIM=512, NH=8, HD=64, WIN=8x8 (N=64 tok/window), SHIFT=(4,4)
// windows: 2048 ; rows M = 131072

// Scratch (device globals = sanctioned scratch)
__device__ float g_qkv[3u * 2048u * 8u * 64u * 64u];  // [part][win][head][t][d]
__device__ float g_o  [131072u * 512u];               // [m][h*64+d]  (tf32-rounded bits)
__device__ float g_x  [131072u * 512u];               // gathered+rounded A for QKV
__device__ float g_wq [1536u * 512u];                 // rounded qkv_w
__device__ float g_wp [512u * 512u];                  // rounded proj_w

// ---------------------------------------------------------------------------
// helpers
// ---------------------------------------------------------------------------
__device__ __forceinline__ uint32_t f2tf32(float f) {
    uint32_t u;
    asm("cvt.rna.tf32.f32 %0, %1;" : "=r"(u) : "f"(f));
    return u;
}
__device__ __forceinline__ void cp16(uint32_t smem, const void* gmem) {
    asm volatile("cp.async.cg.shared.global [%0], [%1], 16;\n" :: "r"(smem), "l"(gmem));
}
__device__ __forceinline__ void mma_tf32(float* c, const uint32_t* a, const uint32_t* b) {
    asm volatile(
        "mma.sync.aligned.m16n8k8.row.col.f32.tf32.tf32.f32 "
        "{%0,%1,%2,%3}, {%4,%5,%6,%7}, {%8,%9}, {%0,%1,%2,%3};"
        : "+f"(c[0]), "+f"(c[1]), "+f"(c[2]), "+f"(c[3])
        : "r"(a[0]), "r"(a[1]), "r"(a[2]), "r"(a[3]), "r"(b[0]), "r"(b[1]));
}

#define SSTRIDE 36
#define STAGE_F (128 * SSTRIDE * 2)
#define SMEM_BYTES (2 * STAGE_F * 4)   // 73728

// ---------------------------------------------------------------------------
// Kernel 0: prep. Gathers x rows (roll+partition) into g_x with tf32 rounding,
// and rounds qkv_w / proj_w into g_wq / g_wp.
// grid.x = 131072 + 2048 row-CTAs, 128 threads, one float4 per thread.
// ---------------------------------------------------------------------------
__global__ __launch_bounds__(128) void k_prep(const float* __restrict__ x,
                                              const float* __restrict__ qkv_w,
                                              const float* __restrict__ proj_w)
{
    const int bid = blockIdx.x;
    const int tid = threadIdx.x;

    const float* src;
    float* dst;
    if (bid < 131072) {
        int m   = bid;
        int win = m >> 6, t = m & 63;
        int b   = win >> 8;
        int wh  = (win >> 4) & 15;
        int ww  = win & 15;
        int i   = t >> 3, j = t & 7;
        int r   = (wh * 8 + i + 4) & 127;     // roll(-4) gather
        int c   = (ww * 8 + j + 4) & 127;
        src = x + ((size_t)((((b << 7) | r) << 7) | c) << 9);
        dst = g_x + (size_t)m * 512;
    } else {
        int w = bid - 131072;                  // 0..2047
        if (w < 1536) { src = qkv_w + (size_t)w * 512;          dst = g_wq + (size_t)w * 512; }
        else          { src = proj_w + (size_t)(w - 1536) * 512; dst = g_wp + (size_t)(w - 1536) * 512; }
    }

    float4 v = ((const float4*)src)[tid];
    uint4 u;
    u.x = f2tf32(v.x); u.y = f2tf32(v.y); u.z = f2tf32(v.z); u.w = f2tf32(v.w);
    ((uint4*)dst)[tid] = u;
}

// ---------------------------------------------------------------------------
// Kernel 1: QKV GEMM (tf32, pre-rounded operands -> no cvt in hot loop).
//   qkv[m,n] = sum_k g_x[m,k]*g_wq[n,k] + qkv_b[n];  M=131072 K=512 N=1536
// ---------------------------------------------------------------------------
__global__ __launch_bounds__(256, 2) void k_qkv_gemm(const float* __restrict__ bias)
{
    extern __shared__ float sm[];

    const int tid   = threadIdx.x;
    const int nTile = blockIdx.x;
    const int mTile = blockIdx.y;

    const int warpId = tid >> 5, lane = tid & 31;
    const int warpM  = warpId & 3;
    const int warpN  = warpId >> 2;
    const int n0     = nTile * 128;
    const int r      = lane >> 2, cq = lane & 3;

    float acc[2][8][4];
#pragma unroll
    for (int mi = 0; mi < 2; mi++)
#pragma unroll
        for (int ni = 0; ni < 8; ni++)
#pragma unroll
            for (int e = 0; e < 4; e++) acc[mi][ni][e] = 0.f;

    auto loadStage = [&](int stage, int k0) {
        float* As = sm + stage * STAGE_F;
        float* Bs = As + 128 * SSTRIDE;
#pragma unroll
        for (int it = 0; it < 4; it++) {
            int ch = tid + it * 256;
            int row = ch >> 3, ci = ch & 7;
            uint32_t sa = (uint32_t)__cvta_generic_to_shared(As + row * SSTRIDE + ci * 4);
            cp16(sa, g_x + (size_t)(mTile * 128 + row) * 512 + k0 + ci * 4);
            uint32_t sb = (uint32_t)__cvta_generic_to_shared(Bs + row * SSTRIDE + ci * 4);
            cp16(sb, g_wq + (size_t)(n0 + row) * 512 + k0 + ci * 4);
        }
    };

    loadStage(0, 0);
    asm volatile("cp.async.commit_group;\n");

    for (int kt = 0; kt < 16; kt++) {
        if (kt < 15) {
            loadStage((kt + 1) & 1, (kt + 1) * 32);
            asm volatile("cp.async.commit_group;\n");
            asm volatile("cp.async.wait_group 1;\n");
        } else {
            asm volatile("cp.async.wait_group 0;\n");
        }
        __syncthreads();

        const uint32_t* As = (const uint32_t*)(sm + (kt & 1) * STAGE_F);
        const uint32_t* Bs = As + 128 * SSTRIDE;
#pragma unroll
        for (int ks = 0; ks < 4; ks++) {
            uint32_t af[2][4];
#pragma unroll
            for (int mi = 0; mi < 2; mi++) {
                const uint32_t* ap = As + (warpM * 32 + mi * 16 + r) * SSTRIDE + ks * 8 + cq;
                af[mi][0] = ap[0];
                af[mi][1] = ap[8 * SSTRIDE];
                af[mi][2] = ap[4];
                af[mi][3] = ap[8 * SSTRIDE + 4];
            }
#pragma unroll
            for (int ni = 0; ni < 8; ni++) {
                const uint32_t* bp = Bs + (warpN * 64 + ni * 8 + r) * SSTRIDE + ks * 8 + cq;
                uint32_t bf[2];
                bf[0] = bp[0];
                bf[1] = bp[4];
                mma_tf32(acc[0][ni], af[0], bf);
                mma_tf32(acc[1][ni], af[1], bf);
            }
        }
        __syncthreads();
    }

    // Epilogue: bias + scatter into g_qkv[part][win][h][t][d]
#pragma unroll
    for (int ni = 0; ni < 8; ni++) {
        int n  = n0 + warpN * 64 + ni * 8 + 2 * cq;
        float b0 = bias[n], b1 = bias[n + 1];
        int part = n >> 9;
        int h    = (n >> 6) & 7;
        int d0   = n & 63;
#pragma unroll
        for (int mi = 0; mi < 2; mi++) {
#pragma unroll
            for (int rr = 0; rr < 2; rr++) {
                int m   = mTile * 128 + warpM * 32 + mi * 16 + r + rr * 8;
                int win = m >> 6, t = m & 63;
                size_t idx = ((((size_t)part * 2048 + win) * 8 + h) * 64 + t) * 64 + d0;
                float2 v = make_float2(acc[mi][ni][rr * 2 + 0] + b0,
                                       acc[mi][ni][rr * 2 + 1] + b1);
                *(float2*)(g_qkv + idx) = v;
            }
        }
    }
}

// ---------------------------------------------------------------------------
// Kernel 2: per (window, head) attention on tensor cores (tf32 mma).
// Output writes are tf32-rounded so proj consumes them without cvts.
// ---------------------------------------------------------------------------
#define AST 68

__global__ __launch_bounds__(128) void k_attn_mma()
{
    __shared__ float Qb[64 * AST];
    __shared__ float Kb[64 * AST];

    const int tid  = threadIdx.x;
    const int warp = tid >> 5;
    const int lane = tid & 31;
    const int r    = lane >> 2;
    const int c    = lane & 3;
    const int m0   = warp * 16;

    const int win = blockIdx.x >> 3;
    const int h   = blockIdx.x & 7;

    const size_t qbase = ((size_t)win * 8 + h) * 4096;
    const float4* qg = (const float4*)(g_qkv + qbase);
    const float4* kg = (const float4*)(g_qkv + (size_t)2048 * 8 * 4096 + qbase);
    const float4* vg = (const float4*)(g_qkv + (size_t)2 * 2048 * 8 * 4096 + qbase);

#pragma unroll
    for (int it = 0; it < 8; it++) {
        int e4 = tid + it * 128;
        int t  = e4 >> 4;
        int d4 = (e4 & 15) * 4;
        *(float4*)(Qb + t * AST + d4) = qg[e4];
        *(float4*)(Kb + t * AST + d4) = kg[e4];
    }
    __syncthreads();

    const float L2_10000 = 13.287712379549449f;
#pragma unroll
    for (int it = 0; it < 16; it++) {
        int p = tid + it * 128;
        int t = p >> 5, q = p & 31;
        int db = (q < 16) ? q : (q + 16);
        int e  = db & 15;
        float pos = (db < 32) ? (float)(t >> 3) : (float)(t & 7);
        float inv = exp2f(-(float)e * (L2_10000 / 16.f));
        float ang = pos * inv;
        float cv = cosf(ang), sv = sinf(ang);

        float a = Qb[t * AST + db], b = Qb[t * AST + db + 16];
        Qb[t * AST + db]      = (a * cv - b * sv) * 0.125f;
        Qb[t * AST + db + 16] = (b * cv + a * sv) * 0.125f;

        a = Kb[t * AST + db]; b = Kb[t * AST + db + 16];
        Kb[t * AST + db]      = a * cv - b * sv;
        Kb[t * AST + db + 16] = b * cv + a * sv;
    }
    __syncthreads();

    // ---- S = Q K^T ----
    uint32_t areg[8][4];
#pragma unroll
    for (int ks = 0; ks < 8; ks++) {
        const float* ap = Qb + (m0 + r) * AST + ks * 8 + c;
        areg[ks][0] = f2tf32(ap[0]);
        areg[ks][1] = f2tf32(ap[8 * AST]);
        areg[ks][2] = f2tf32(ap[4]);
        areg[ks][3] = f2tf32(ap[8 * AST + 4]);
    }

    float sacc[8][4];
#pragma unroll
    for (int ni = 0; ni < 8; ni++)
#pragma unroll
        for (int e = 0; e < 4; e++) sacc[ni][e] = 0.f;

#pragma unroll
    for (int ni = 0; ni < 8; ni++) {
        const float* bbase = Kb + (ni * 8 + r) * AST + c;
#pragma unroll
        for (int ks = 0; ks < 8; ks++) {
            uint32_t bf[2];
            bf[0] = f2tf32(bbase[ks * 8]);
            bf[1] = f2tf32(bbase[ks * 8 + 4]);
            mma_tf32(sacc[ni], areg[ks], bf);
        }
    }
    __syncthreads();

    // ---- V load into Kb ----
#pragma unroll
    for (int it = 0; it < 8; it++) {
        int e4 = tid + it * 128;
        int t  = e4 >> 4;
        int d4 = (e4 & 15) * 4;
        *(float4*)(Kb + t * AST + d4) = vg[e4];
    }

    // ---- mask + softmax in registers ----
    const bool maskOn = (((win >> 4) & 15) == 15);
    const bool warpLo = (warp < 2);

    float mx1 = -1e30f, mx2 = -1e30f;
#pragma unroll
    for (int ni = 0; ni < 8; ni++) {
        float msub = (maskOn && ((ni < 4) != warpLo)) ? 100.f : 0.f;
        sacc[ni][0] -= msub; sacc[ni][1] -= msub;
        sacc[ni][2] -= msub; sacc[ni][3] -= msub;
        mx1 = fmaxf(mx1, fmaxf(sacc[ni][0], sacc[ni][1]));
        mx2 = fmaxf(mx2, fmaxf(sacc[ni][2], sacc[ni][3]));
    }
    mx1 = fmaxf(mx1, __shfl_xor_sync(0xffffffffu, mx1, 1));
    mx1 = fmaxf(mx1, __shfl_xor_sync(0xffffffffu, mx1, 2));
    mx2 = fmaxf(mx2, __shfl_xor_sync(0xffffffffu, mx2, 1));
    mx2 = fmaxf(mx2, __shfl_xor_sync(0xffffffffu, mx2, 2));

    float s1 = 0.f, s2 = 0.f;
#pragma unroll
    for (int ni = 0; ni < 8; ni++) {
        sacc[ni][0] = __expf(sacc[ni][0] - mx1);
        sacc[ni][1] = __expf(sacc[ni][1] - mx1);
        sacc[ni][2] = __expf(sacc[ni][2] - mx2);
        sacc[ni][3] = __expf(sacc[ni][3] - mx2);
        s1 += sacc[ni][0] + sacc[ni][1];
        s2 += sacc[ni][2] + sacc[ni][3];
    }
    s1 += __shfl_xor_sync(0xffffffffu, s1, 1);
    s1 += __shfl_xor_sync(0xffffffffu, s1, 2);
    s2 += __shfl_xor_sync(0xffffffffu, s2, 1);
    s2 += __shfl_xor_sync(0xffffffffu, s2, 2);
    const float i1 = 1.f / s1, i2 = 1.f / s2;

#pragma unroll
    for (int ni = 0; ni < 8; ni++) {
        *(float2*)(Qb + (m0 + r) * AST + ni * 8 + 2 * c) =
            make_float2(sacc[ni][0] * i1, sacc[ni][1] * i1);
        *(float2*)(Qb + (m0 + r + 8) * AST + ni * 8 + 2 * c) =
            make_float2(sacc[ni][2] * i2, sacc[ni][3] * i2);
    }
    __syncthreads();

    // ---- O = P V ----
    uint32_t preg[8][4];
#pragma unroll
    for (int ks = 0; ks < 8; ks++) {
        const float* pp = Qb + (m0 + r) * AST + ks * 8 + c;
        preg[ks][0] = f2tf32(pp[0]);
        preg[ks][1] = f2tf32(pp[8 * AST]);
        preg[ks][2] = f2tf32(pp[4]);
        preg[ks][3] = f2tf32(pp[8 * AST + 4]);
    }

    float oacc[8][4];
#pragma unroll
    for (int ni = 0; ni < 8; ni++)
#pragma unroll
        for (int e = 0; e < 4; e++) oacc[ni][e] = 0.f;

#pragma unroll
    for (int ni = 0; ni < 8; ni++) {
        const float* vb = Kb + c * AST + ni * 8 + r;
#pragma unroll
        for (int ks = 0; ks < 8; ks++) {
            uint32_t bf[2];
            bf[0] = f2tf32(vb[ks * 8 * AST]);
            bf[1] = f2tf32(vb[(ks * 8 + 4) * AST]);
            mma_tf32(oacc[ni], preg[ks], bf);
        }
    }

    // write O (tf32-rounded bits) to g_o[m][h*64+d]
    uint32_t* go32 = (uint32_t*)g_o;
    const size_t mrow1 = (size_t)win * 64 + m0 + r;
    const size_t mrow2 = mrow1 + 8;
#pragma unroll
    for (int ni = 0; ni < 8; ni++) {
        int d0 = h * 64 + ni * 8 + 2 * c;
        uint2 v1 = make_uint2(f2tf32(oacc[ni][0]), f2tf32(oacc[ni][1]));
        uint2 v2 = make_uint2(f2tf32(oacc[ni][2]), f2tf32(oacc[ni][3]));
        *(uint2*)(go32 + mrow1 * 512 + d0) = v1;
        *(uint2*)(go32 + mrow2 * 512 + d0) = v2;
    }
}

// ---------------------------------------------------------------------------
// Kernel 3: proj GEMM (tf32, pre-rounded) + bias + unpartition/roll scatter.
// ---------------------------------------------------------------------------
__global__ __launch_bounds__(256, 2) void k_proj_gemm(const float* __restrict__ bias,
                                                      float* __restrict__ out)
{
    extern __shared__ float sm[];

    const int tid   = threadIdx.x;
    const int nTile = blockIdx.x;
    const int mTile = blockIdx.y;

    const int warpId = tid >> 5, lane = tid & 31;
    const int warpM  = warpId & 3;
    const int warpN  = warpId >> 2;
    const int n0     = nTile * 128;
    const int r      = lane >> 2, cq = lane & 3;

    float acc[2][8][4];
#pragma unroll
    for (int mi = 0; mi < 2; mi++)
#pragma unroll
        for (int ni = 0; ni < 8; ni++)
#pragma unroll
            for (int e = 0; e < 4; e++) acc[mi][ni][e] = 0.f;

    auto loadStage = [&](int stage, int k0) {
        float* As = sm + stage * STAGE_F;
        float* Bs = As + 128 * SSTRIDE;
#pragma unroll
        for (int it = 0; it < 4; it++) {
            int ch = tid + it * 256;
            int row = ch >> 3, ci = ch & 7;
            uint32_t sa = (uint32_t)__cvta_generic_to_shared(As + row * SSTRIDE + ci * 4);
            cp16(sa, g_o + (size_t)(mTile * 128 + row) * 512 + k0 + ci * 4);
            uint32_t sb = (uint32_t)__cvta_generic_to_shared(Bs + row * SSTRIDE + ci * 4);
            cp16(sb, g_wp + (size_t)(n0 + row) * 512 + k0 + ci * 4);
        }
    };

    loadStage(0, 0);
    asm volatile("cp.async.commit_group;\n");

    for (int kt = 0; kt < 16; kt++) {
        if (kt < 15) {
            loadStage((kt + 1) & 1, (kt + 1) * 32);
            asm volatile("cp.async.commit_group;\n");
            asm volatile("cp.async.wait_group 1;\n");
        } else {
            asm volatile("cp.async.wait_group 0;\n");
        }
        __syncthreads();

        const uint32_t* As = (const uint32_t*)(sm + (kt & 1) * STAGE_F);
        const uint32_t* Bs = As + 128 * SSTRIDE;
#pragma unroll
        for (int ks = 0; ks < 4; ks++) {
            uint32_t af[2][4];
#pragma unroll
            for (int mi = 0; mi < 2; mi++) {
                const uint32_t* ap = As + (warpM * 32 + mi * 16 + r) * SSTRIDE + ks * 8 + cq;
                af[mi][0] = ap[0];
                af[mi][1] = ap[8 * SSTRIDE];
                af[mi][2] = ap[4];
                af[mi][3] = ap[8 * SSTRIDE + 4];
            }
#pragma unroll
            for (int ni = 0; ni < 8; ni++) {
                const uint32_t* bp = Bs + (warpN * 64 + ni * 8 + r) * SSTRIDE + ks * 8 + cq;
                uint32_t bf[2];
                bf[0] = bp[0];
                bf[1] = bp[4];
                mma_tf32(acc[0][ni], af[0], bf);
                mma_tf32(acc[1][ni], af[1], bf);
            }
        }
        __syncthreads();
    }

#pragma unroll
    for (int ni = 0; ni < 8; ni++) {
        int n  = n0 + warpN * 64 + ni * 8 + 2 * cq;
        float b0 = bias[n], b1 = bias[n + 1];
#pragma unroll
        for (int mi = 0; mi < 2; mi++) {
#pragma unroll
            for (int rr2 = 0; rr2 < 2; rr2++) {
                int m   = mTile * 128 + warpM * 32 + mi * 16 + r + rr2 * 8;
                int win = m >> 6, t = m & 63;
                int b   = win >> 8;
                int wh  = (win >> 4) & 15;
                int ww  = win & 15;
                int ii  = t >> 3, jj = t & 7;
                int rO  = (wh * 8 + ii + 4) & 127;
                int cO  = (ww * 8 + jj + 4) & 127;
                size_t off = ((((size_t)b << 7) | rO) << 7 | cO) << 9;
                float2 v = make_float2(acc[mi][ni][rr2 * 2 + 0] + b0,
                                       acc[mi][ni][rr2 * 2 + 1] + b1);
                *(float2*)(out + off + n) = v;
            }
        }
    }
}

// ---------------------------------------------------------------------------
extern "C" void kernel_launch(void* const* d_in, const int* in_sizes, int n_in,
                              void* d_out, int out_size)
{
    const float* x      = (const float*)d_in[0];
    const float* qkv_w  = (const float*)d_in[1];
    const float* qkv_b  = (const float*)d_in[2];
    const float* proj_w = (const float*)d_in[3];
    const float* proj_b = (const float*)d_in[4];
    float* out = (float*)d_out;

    cudaFuncSetAttribute(k_qkv_gemm,  cudaFuncAttributeMaxDynamicSharedMemorySize, SMEM_BYTES);
    cudaFuncSetAttribute(k_proj_gemm, cudaFuncAttributeMaxDynamicSharedMemorySize, SMEM_BYTES);

    k_prep<<<131072 + 2048, 128>>>(x, qkv_w, proj_w);
    k_qkv_gemm<<<dim3(12, 1024), 256, SMEM_BYTES>>>(qkv_b);
    k_attn_mma<<<2048 * 8, 128>>>();
    k_proj_gemm<<<dim3(4, 1024), 256, SMEM_BYTES>>>(proj_b, out);
}

// round 6
// speedup vs baseline: 4.6854x; 1.0019x over previous
#include <cuda_runtime.h>
#include <cstdint>

// Problem constants:
// B=8, H=W=128, DIM=512, NH=8, HD=64, WIN=8x8 (N=64 tok/window), SHIFT=(4,4)
// windows: 2048 ; rows M = 131072
//
// K-permutation: within every 8-wide K block, operands are stored as
// [k0,k4,k1,k5,k2,k6,k3,k7]. Applied identically to A and B of each GEMM,
// so results are unchanged, but mma fragment k-pairs become contiguous
// (LDS.64 instead of 2x LDS.32).

// Scratch (device globals = sanctioned scratch)
__device__ float g_qkv[3u * 2048u * 8u * 64u * 64u];  // [part][win][head][t][d] (natural)
__device__ float g_o  [131072u * 512u];               // [m][k] (tf32-rounded, K-permuted)
__device__ float g_x  [131072u * 512u];               // gathered, rounded, K-permuted
__device__ float g_wq [1536u * 512u];                 // rounded, K-permuted qkv_w
__device__ float g_wp [512u * 512u];                  // rounded, K-permuted proj_w

// ---------------------------------------------------------------------------
// helpers
// ---------------------------------------------------------------------------
__device__ __forceinline__ uint32_t f2tf32(float f) {
    uint32_t u;
    asm("cvt.rna.tf32.f32 %0, %1;" : "=r"(u) : "f"(f));
    return u;
}
__device__ __forceinline__ void cp16(uint32_t smem, const void* gmem) {
    asm volatile("cp.async.cg.shared.global [%0], [%1], 16;\n" :: "r"(smem), "l"(gmem));
}
__device__ __forceinline__ void mma_tf32(float* c, const uint32_t* a, const uint32_t* b) {
    asm volatile(
        "mma.sync.aligned.m16n8k8.row.col.f32.tf32.tf32.f32 "
        "{%0,%1,%2,%3}, {%4,%5,%6,%7}, {%8,%9}, {%0,%1,%2,%3};"
        : "+f"(c[0]), "+f"(c[1]), "+f"(c[2]), "+f"(c[3])
        : "r"(a[0]), "r"(a[1]), "r"(a[2]), "r"(a[3]), "r"(b[0]), "r"(b[1]));
}

#define SSTRIDE 40            // 32 floats + 8 pad: float2 frag loads conflict-free
#define STAGE_F (128 * SSTRIDE * 2)   // floats per stage (A + B)
#define SMEM_BYTES (2 * STAGE_F * 4)  // 81920

// ---------------------------------------------------------------------------
// Kernel 0: prep — gather x (roll+partition) into g_x, round to tf32, apply
// K-permutation. Same rounding+permutation for qkv_w / proj_w.
// Each thread produces one permuted float4 (out positions 4t..4t+3).
// out[8b+2c] = in[8b+c], out[8b+2c+1] = in[8b+c+4]
// ---------------------------------------------------------------------------
__global__ __launch_bounds__(128) void k_prep(const float* __restrict__ x,
                                              const float* __restrict__ qkv_w,
                                              const float* __restrict__ proj_w)
{
    const int bid = blockIdx.x;
    const int tid = threadIdx.x;

    const float* src;
    float* dst;
    if (bid < 131072) {
        int m   = bid;
        int win = m >> 6, t = m & 63;
        int b   = win >> 8;
        int wh  = (win >> 4) & 15;
        int ww  = win & 15;
        int i   = t >> 3, j = t & 7;
        int r   = (wh * 8 + i + 4) & 127;     // roll(-4) gather
        int c   = (ww * 8 + j + 4) & 127;
        src = x + ((size_t)((((b << 7) | r) << 7) | c) << 9);
        dst = g_x + (size_t)m * 512;
    } else {
        int w = bid - 131072;
        if (w < 1536) { src = qkv_w + (size_t)w * 512;           dst = g_wq + (size_t)w * 512; }
        else          { src = proj_w + (size_t)(w - 1536) * 512; dst = g_wp + (size_t)(w - 1536) * 512; }
    }

    // out float4 at 4*tid; input block b8 = 8*(tid>>1), sub = tid&1
    int base = 8 * (tid >> 1) + 2 * (tid & 1);
    float2 lo = *(const float2*)(src + base);       // in[c], in[c+1]
    float2 hi = *(const float2*)(src + base + 4);   // in[c+4], in[c+5]
    uint4 u;
    u.x = f2tf32(lo.x); u.y = f2tf32(hi.x);
    u.z = f2tf32(lo.y); u.w = f2tf32(hi.y);
    ((uint4*)dst)[tid] = u;
}

// ---------------------------------------------------------------------------
// Kernel 1: QKV GEMM (tf32, pre-rounded + K-permuted -> LDS.64 frag loads).
//   qkv[m,n] = sum_k g_x[m,k]*g_wq[n,k] + qkv_b[n];  M=131072 K=512 N=1536
// BM=BN=128, BK=32, 8 warps (4M x 2N), warp tile 32x64.
// ---------------------------------------------------------------------------
__global__ __launch_bounds__(256, 2) void k_qkv_gemm(const float* __restrict__ bias)
{
    extern __shared__ float sm[];

    const int tid   = threadIdx.x;
    const int nTile = blockIdx.x;
    const int mTile = blockIdx.y;

    const int warpId = tid >> 5, lane = tid & 31;
    const int warpM  = warpId & 3;
    const int warpN  = warpId >> 2;
    const int n0     = nTile * 128;
    const int r      = lane >> 2, cq = lane & 3;

    float acc[2][8][4];
#pragma unroll
    for (int mi = 0; mi < 2; mi++)
#pragma unroll
        for (int ni = 0; ni < 8; ni++)
#pragma unroll
            for (int e = 0; e < 4; e++) acc[mi][ni][e] = 0.f;

    auto loadStage = [&](int stage, int k0) {
        float* As = sm + stage * STAGE_F;
        float* Bs = As + 128 * SSTRIDE;
#pragma unroll
        for (int it = 0; it < 4; it++) {
            int ch = tid + it * 256;
            int row = ch >> 3, ci = ch & 7;
            uint32_t sa = (uint32_t)__cvta_generic_to_shared(As + row * SSTRIDE + ci * 4);
            cp16(sa, g_x + (size_t)(mTile * 128 + row) * 512 + k0 + ci * 4);
            uint32_t sb = (uint32_t)__cvta_generic_to_shared(Bs + row * SSTRIDE + ci * 4);
            cp16(sb, g_wq + (size_t)(n0 + row) * 512 + k0 + ci * 4);
        }
    };

    loadStage(0, 0);
    asm volatile("cp.async.commit_group;\n");

    for (int kt = 0; kt < 16; kt++) {
        if (kt < 15) {
            loadStage((kt + 1) & 1, (kt + 1) * 32);
            asm volatile("cp.async.commit_group;\n");
            asm volatile("cp.async.wait_group 1;\n");
        } else {
            asm volatile("cp.async.wait_group 0;\n");
        }
        __syncthreads();

        const uint32_t* As = (const uint32_t*)(sm + (kt & 1) * STAGE_F);
        const uint32_t* Bs = As + 128 * SSTRIDE;
#pragma unroll
        for (int ks = 0; ks < 4; ks++) {
            uint32_t af[2][4];
#pragma unroll
            for (int mi = 0; mi < 2; mi++) {
                const uint32_t* ap = As + (warpM * 32 + mi * 16 + r) * SSTRIDE + ks * 8 + 2 * cq;
                uint2 lo = *(const uint2*)ap;                 // (k=c, k=c+4) row r
                uint2 hi = *(const uint2*)(ap + 8 * SSTRIDE); // row r+8
                af[mi][0] = lo.x; af[mi][1] = hi.x;
                af[mi][2] = lo.y; af[mi][3] = hi.y;
            }
#pragma unroll
            for (int ni = 0; ni < 8; ni++) {
                uint2 bq = *(const uint2*)(Bs + (warpN * 64 + ni * 8 + r) * SSTRIDE + ks * 8 + 2 * cq);
                uint32_t bf[2] = { bq.x, bq.y };
                mma_tf32(acc[0][ni], af[0], bf);
                mma_tf32(acc[1][ni], af[1], bf);
            }
        }
        __syncthreads();
    }

    // Epilogue: bias + scatter into g_qkv[part][win][h][t][d] (natural order)
#pragma unroll
    for (int ni = 0; ni < 8; ni++) {
        int n  = n0 + warpN * 64 + ni * 8 + 2 * cq;
        float b0 = bias[n], b1 = bias[n + 1];
        int part = n >> 9;
        int h    = (n >> 6) & 7;
        int d0   = n & 63;
#pragma unroll
        for (int mi = 0; mi < 2; mi++) {
#pragma unroll
            for (int rr = 0; rr < 2; rr++) {
                int m   = mTile * 128 + warpM * 32 + mi * 16 + r + rr * 8;
                int win = m >> 6, t = m & 63;
                size_t idx = ((((size_t)part * 2048 + win) * 8 + h) * 64 + t) * 64 + d0;
                float2 v = make_float2(acc[mi][ni][rr * 2 + 0] + b0,
                                       acc[mi][ni][rr * 2 + 1] + b1);
                *(float2*)(g_qkv + idx) = v;
            }
        }
    }
}

// ---------------------------------------------------------------------------
// Kernel 2: per (window, head) attention on tensor cores (tf32 mma.sync).
// Writes tf32-rounded, K-PERMUTED O so proj consumes it with LDS.64 frags.
// ---------------------------------------------------------------------------
#define AST 68

__global__ __launch_bounds__(128) void k_attn_mma()
{
    __shared__ float Qb[64 * AST];
    __shared__ float Kb[64 * AST];

    const int tid  = threadIdx.x;
    const int warp = tid >> 5;
    const int lane = tid & 31;
    const int r    = lane >> 2;
    const int c    = lane & 3;
    const int m0   = warp * 16;

    const int win = blockIdx.x >> 3;
    const int h   = blockIdx.x & 7;

    const size_t qbase = ((size_t)win * 8 + h) * 4096;
    const float4* qg = (const float4*)(g_qkv + qbase);
    const float4* kg = (const float4*)(g_qkv + (size_t)2048 * 8 * 4096 + qbase);
    const float4* vg = (const float4*)(g_qkv + (size_t)2 * 2048 * 8 * 4096 + qbase);

#pragma unroll
    for (int it = 0; it < 8; it++) {
        int e4 = tid + it * 128;
        int t  = e4 >> 4;
        int d4 = (e4 & 15) * 4;
        *(float4*)(Qb + t * AST + d4) = qg[e4];
        *(float4*)(Kb + t * AST + d4) = kg[e4];
    }
    __syncthreads();

    const float L2_10000 = 13.287712379549449f;
#pragma unroll
    for (int it = 0; it < 16; it++) {
        int p = tid + it * 128;
        int t = p >> 5, q = p & 31;
        int db = (q < 16) ? q : (q + 16);
        int e  = db & 15;
        float pos = (db < 32) ? (float)(t >> 3) : (float)(t & 7);
        float inv = exp2f(-(float)e * (L2_10000 / 16.f));
        float ang = pos * inv;
        float cv = cosf(ang), sv = sinf(ang);

        float a = Qb[t * AST + db], b = Qb[t * AST + db + 16];
        Qb[t * AST + db]      = (a * cv - b * sv) * 0.125f;
        Qb[t * AST + db + 16] = (b * cv + a * sv) * 0.125f;

        a = Kb[t * AST + db]; b = Kb[t * AST + db + 16];
        Kb[t * AST + db]      = a * cv - b * sv;
        Kb[t * AST + db + 16] = b * cv + a * sv;
    }
    __syncthreads();

    uint32_t areg[8][4];
#pragma unroll
    for (int ks = 0; ks < 8; ks++) {
        const float* ap = Qb + (m0 + r) * AST + ks * 8 + c;
        areg[ks][0] = f2tf32(ap[0]);
        areg[ks][1] = f2tf32(ap[8 * AST]);
        areg[ks][2] = f2tf32(ap[4]);
        areg[ks][3] = f2tf32(ap[8 * AST + 4]);
    }

    float sacc[8][4];
#pragma unroll
    for (int ni = 0; ni < 8; ni++)
#pragma unroll
        for (int e = 0; e < 4; e++) sacc[ni][e] = 0.f;

#pragma unroll
    for (int ni = 0; ni < 8; ni++) {
        const float* bbase = Kb + (ni * 8 + r) * AST + c;
#pragma unroll
        for (int ks = 0; ks < 8; ks++) {
            uint32_t bf[2];
            bf[0] = f2tf32(bbase[ks * 8]);
            bf[1] = f2tf32(bbase[ks * 8 + 4]);
            mma_tf32(sacc[ni], areg[ks], bf);
        }
    }
    __syncthreads();

#pragma unroll
    for (int it = 0; it < 8; it++) {
        int e4 = tid + it * 128;
        int t  = e4 >> 4;
        int d4 = (e4 & 15) * 4;
        *(float4*)(Kb + t * AST + d4) = vg[e4];
    }

    const bool maskOn = (((win >> 4) & 15) == 15);
    const bool warpLo = (warp < 2);

    float mx1 = -1e30f, mx2 = -1e30f;
#pragma unroll
    for (int ni = 0; ni < 8; ni++) {
        float msub = (maskOn && ((ni < 4) != warpLo)) ? 100.f : 0.f;
        sacc[ni][0] -= msub; sacc[ni][1] -= msub;
        sacc[ni][2] -= msub; sacc[ni][3] -= msub;
        mx1 = fmaxf(mx1, fmaxf(sacc[ni][0], sacc[ni][1]));
        mx2 = fmaxf(mx2, fmaxf(sacc[ni][2], sacc[ni][3]));
    }
    mx1 = fmaxf(mx1, __shfl_xor_sync(0xffffffffu, mx1, 1));
    mx1 = fmaxf(mx1, __shfl_xor_sync(0xffffffffu, mx1, 2));
    mx2 = fmaxf(mx2, __shfl_xor_sync(0xffffffffu, mx2, 1));
    mx2 = fmaxf(mx2, __shfl_xor_sync(0xffffffffu, mx2, 2));

    float s1 = 0.f, s2 = 0.f;
#pragma unroll
    for (int ni = 0; ni < 8; ni++) {
        sacc[ni][0] = __expf(sacc[ni][0] - mx1);
        sacc[ni][1] = __expf(sacc[ni][1] - mx1);
        sacc[ni][2] = __expf(sacc[ni][2] - mx2);
        sacc[ni][3] = __expf(sacc[ni][3] - mx2);
        s1 += sacc[ni][0] + sacc[ni][1];
        s2 += sacc[ni][2] + sacc[ni][3];
    }
    s1 += __shfl_xor_sync(0xffffffffu, s1, 1);
    s1 += __shfl_xor_sync(0xffffffffu, s1, 2);
    s2 += __shfl_xor_sync(0xffffffffu, s2, 1);
    s2 += __shfl_xor_sync(0xffffffffu, s2, 2);
    const float i1 = 1.f / s1, i2 = 1.f / s2;

#pragma unroll
    for (int ni = 0; ni < 8; ni++) {
        *(float2*)(Qb + (m0 + r) * AST + ni * 8 + 2 * c) =
            make_float2(sacc[ni][0] * i1, sacc[ni][1] * i1);
        *(float2*)(Qb + (m0 + r + 8) * AST + ni * 8 + 2 * c) =
            make_float2(sacc[ni][2] * i2, sacc[ni][3] * i2);
    }
    __syncthreads();

    uint32_t preg[8][4];
#pragma unroll
    for (int ks = 0; ks < 8; ks++) {
        const float* pp = Qb + (m0 + r) * AST + ks * 8 + c;
        preg[ks][0] = f2tf32(pp[0]);
        preg[ks][1] = f2tf32(pp[8 * AST]);
        preg[ks][2] = f2tf32(pp[4]);
        preg[ks][3] = f2tf32(pp[8 * AST + 4]);
    }

    float oacc[8][4];
#pragma unroll
    for (int ni = 0; ni < 8; ni++)
#pragma unroll
        for (int e = 0; e < 4; e++) oacc[ni][e] = 0.f;

#pragma unroll
    for (int ni = 0; ni < 8; ni++) {
        const float* vb = Kb + c * AST + ni * 8 + r;
#pragma unroll
        for (int ks = 0; ks < 8; ks++) {
            uint32_t bf[2];
            bf[0] = f2tf32(vb[ks * 8 * AST]);
            bf[1] = f2tf32(vb[(ks * 8 + 4) * AST]);
            mma_tf32(oacc[ni], preg[ks], bf);
        }
    }

    // write O (tf32-rounded, K-PERMUTED) to g_o[m][...]
    // old col j -> new pos: j<4 ? 2j : 2(j-4)+1. Thread holds old cols
    // (2c, 2c+1); new positions are (dp, dp+2) with dp = ((c&1)<<2)|(c>>1).
    uint32_t* go32 = (uint32_t*)g_o;
    const int dp = ((c & 1) << 2) | (c >> 1);
    const size_t mrow1 = (size_t)win * 64 + m0 + r;
    const size_t mrow2 = mrow1 + 8;
#pragma unroll
    for (int ni = 0; ni < 8; ni++) {
        int d0 = h * 64 + ni * 8 + dp;
        go32[mrow1 * 512 + d0]     = f2tf32(oacc[ni][0]);
        go32[mrow1 * 512 + d0 + 2] = f2tf32(oacc[ni][1]);
        go32[mrow2 * 512 + d0]     = f2tf32(oacc[ni][2]);
        go32[mrow2 * 512 + d0 + 2] = f2tf32(oacc[ni][3]);
    }
}

// ---------------------------------------------------------------------------
// Kernel 3: proj GEMM (tf32, pre-rounded + K-permuted) + bias + scatter.
// ---------------------------------------------------------------------------
__global__ __launch_bounds__(256, 2) void k_proj_gemm(const float* __restrict__ bias,
                                                      float* __restrict__ out)
{
    extern __shared__ float sm[];

    const int tid   = threadIdx.x;
    const int nTile = blockIdx.x;
    const int mTile = blockIdx.y;

    const int warpId = tid >> 5, lane = tid & 31;
    const int warpM  = warpId & 3;
    const int warpN  = warpId >> 2;
    const int n0     = nTile * 128;
    const int r      = lane >> 2, cq = lane & 3;

    float acc[2][8][4];
#pragma unroll
    for (int mi = 0; mi < 2; mi++)
#pragma unroll
        for (int ni = 0; ni < 8; ni++)
#pragma unroll
            for (int e = 0; e < 4; e++) acc[mi][ni][e] = 0.f;

    auto loadStage = [&](int stage, int k0) {
        float* As = sm + stage * STAGE_F;
        float* Bs = As + 128 * SSTRIDE;
#pragma unroll
        for (int it = 0; it < 4; it++) {
            int ch = tid + it * 256;
            int row = ch >> 3, ci = ch & 7;
            uint32_t sa = (uint32_t)__cvta_generic_to_shared(As + row * SSTRIDE + ci * 4);
            cp16(sa, g_o + (size_t)(mTile * 128 + row) * 512 + k0 + ci * 4);
            uint32_t sb = (uint32_t)__cvta_generic_to_shared(Bs + row * SSTRIDE + ci * 4);
            cp16(sb, g_wp + (size_t)(n0 + row) * 512 + k0 + ci * 4);
        }
    };

    loadStage(0, 0);
    asm volatile("cp.async.commit_group;\n");

    for (int kt = 0; kt < 16; kt++) {
        if (kt < 15) {
            loadStage((kt + 1) & 1, (kt + 1) * 32);
            asm volatile("cp.async.commit_group;\n");
            asm volatile("cp.async.wait_group 1;\n");
        } else {
            asm volatile("cp.async.wait_group 0;\n");
        }
        __syncthreads();

        const uint32_t* As = (const uint32_t*)(sm + (kt & 1) * STAGE_F);
        const uint32_t* Bs = As + 128 * SSTRIDE;
#pragma unroll
        for (int ks = 0; ks < 4; ks++) {
            uint32_t af[2][4];
#pragma unroll
            for (int mi = 0; mi < 2; mi++) {
                const uint32_t* ap = As + (warpM * 32 + mi * 16 + r) * SSTRIDE + ks * 8 + 2 * cq;
                uint2 lo = *(const uint2*)ap;
                uint2 hi = *(const uint2*)(ap + 8 * SSTRIDE);
                af[mi][0] = lo.x; af[mi][1] = hi.x;
                af[mi][2] = lo.y; af[mi][3] = hi.y;
            }
#pragma unroll
            for (int ni = 0; ni < 8; ni++) {
                uint2 bq = *(const uint2*)(Bs + (warpN * 64 + ni * 8 + r) * SSTRIDE + ks * 8 + 2 * cq);
                uint32_t bf[2] = { bq.x, bq.y };
                mma_tf32(acc[0][ni], af[0], bf);
                mma_tf32(acc[1][ni], af[1], bf);
            }
        }
        __syncthreads();
    }

#pragma unroll
    for (int ni = 0; ni < 8; ni++) {
        int n  = n0 + warpN * 64 + ni * 8 + 2 * cq;
        float b0 = bias[n], b1 = bias[n + 1];
#pragma unroll
        for (int mi = 0; mi < 2; mi++) {
#pragma unroll
            for (int rr2 = 0; rr2 < 2; rr2++) {
                int m   = mTile * 128 + warpM * 32 + mi * 16 + r + rr2 * 8;
                int win = m >> 6, t = m & 63;
                int b   = win >> 8;
                int wh  = (win >> 4) & 15;
                int ww  = win & 15;
                int ii  = t >> 3, jj = t & 7;
                int rO  = (wh * 8 + ii + 4) & 127;
                int cO  = (ww * 8 + jj + 4) & 127;
                size_t off = ((((size_t)b << 7) | rO) << 7 | cO) << 9;
                float2 v = make_float2(acc[mi][ni][rr2 * 2 + 0] + b0,
                                       acc[mi][ni][rr2 * 2 + 1] + b1);
                *(float2*)(out + off + n) = v;
            }
        }
    }
}

// ---------------------------------------------------------------------------
extern "C" void kernel_launch(void* const* d_in, const int* in_sizes, int n_in,
                              void* d_out, int out_size)
{
    const float* x      = (const float*)d_in[0];
    const float* qkv_w  = (const float*)d_in[1];
    const float* qkv_b  = (const float*)d_in[2];
    const float* proj_w = (const float*)d_in[3];
    const float* proj_b = (const float*)d_in[4];
    float* out = (float*)d_out;

    cudaFuncSetAttribute(k_qkv_gemm,  cudaFuncAttributeMaxDynamicSharedMemorySize, SMEM_BYTES);
    cudaFuncSetAttribute(k_proj_gemm, cudaFuncAttributeMaxDynamicSharedMemorySize, SMEM_BYTES);

    k_prep<<<131072 + 2048, 128>>>(x, qkv_w, proj_w);
    k_qkv_gemm<<<dim3(12, 1024), 256, SMEM_BYTES>>>(qkv_b);
    k_attn_mma<<<2048 * 8, 128>>>();
    k_proj_gemm<<<dim3(4, 1024), 256, SMEM_BYTES>>>(proj_b, out);
}

// round 7
// speedup vs baseline: 5.0798x; 1.0842x over previous
#include <cuda_runtime.h>
#include <cstdint>

// Problem constants:
// B=8, H=W=128, DIM=512, NH=8, HD=64, WIN=8x8 (N=64 tok/window), SHIFT=(4,4)
// windows: 2048 ; rows M = 131072

// Scratch (device globals = sanctioned scratch)
__device__ float g_qkv[3u * 2048u * 8u * 64u * 64u];  // [part][win][head][t][d]
__device__ float g_o  [131072u * 512u];               // [m][h*64+d] (tf32-rounded)
__device__ float g_wq [1536u * 512u];                 // rounded qkv_w
__device__ float g_wp [512u * 512u];                  // rounded proj_w

// ---------------------------------------------------------------------------
// helpers
// ---------------------------------------------------------------------------
__device__ __forceinline__ uint32_t f2tf32(float f) {
    uint32_t u;
    asm("cvt.rna.tf32.f32 %0, %1;" : "=r"(u) : "f"(f));
    return u;
}
__device__ __forceinline__ void cp16(uint32_t smem, const void* gmem) {
    asm volatile("cp.async.cg.shared.global [%0], [%1], 16;\n" :: "r"(smem), "l"(gmem));
}
__device__ __forceinline__ void mma_tf32(float* c, const uint32_t* a, const uint32_t* b) {
    asm volatile(
        "mma.sync.aligned.m16n8k8.row.col.f32.tf32.tf32.f32 "
        "{%0,%1,%2,%3}, {%4,%5,%6,%7}, {%8,%9}, {%0,%1,%2,%3};"
        : "+f"(c[0]), "+f"(c[1]), "+f"(c[2]), "+f"(c[3])
        : "r"(a[0]), "r"(a[1]), "r"(a[2]), "r"(a[3]), "r"(b[0]), "r"(b[1]));
}

#define SSTRIDE 36                     // 32 floats + 4 pad, conflict-free frags
#define STAGE_F (128 * SSTRIDE * 2)    // floats per stage (A + B) = 9216
#define SMEM_BYTES (3 * STAGE_F * 4)   // 3 stages = 110592 B -> 2 CTAs/SM

// ---------------------------------------------------------------------------
// Kernel 0: prep — round qkv_w / proj_w to tf32 bits (2048 small CTAs).
// ---------------------------------------------------------------------------
__global__ __launch_bounds__(128) void k_prep_w(const float* __restrict__ qkv_w,
                                                const float* __restrict__ proj_w)
{
    const int w   = blockIdx.x;          // 0..2047
    const int tid = threadIdx.x;
    const float* src;
    float* dst;
    if (w < 1536) { src = qkv_w + (size_t)w * 512;           dst = g_wq + (size_t)w * 512; }
    else          { src = proj_w + (size_t)(w - 1536) * 512; dst = g_wp + (size_t)(w - 1536) * 512; }

    float4 v = ((const float4*)src)[tid];
    uint4 u;
    u.x = f2tf32(v.x); u.y = f2tf32(v.y); u.z = f2tf32(v.z); u.w = f2tf32(v.w);
    ((uint4*)dst)[tid] = u;
}

// ---------------------------------------------------------------------------
// Kernel 1: QKV GEMM (tf32) + fused roll+partition gather on A (raw x).
//   qkv[m,n] = sum_k xw[m,k]*qkv_w[n,k] + qkv_b[n];  M=131072 K=512 N=1536
// BM=BN=128, BK=32, 8 warps (4M x 2N), 3-stage cp.async, 1 barrier/ktile.
// A fragments cvt inline (proven free); B pre-rounded.
// ---------------------------------------------------------------------------
__global__ __launch_bounds__(256, 2) void k_qkv_gemm(const float* __restrict__ x,
                                                     const float* __restrict__ bias)
{
    extern __shared__ float sm[];
    __shared__ int rowOff[128];

    const int tid   = threadIdx.x;
    const int nTile = blockIdx.x;       // fastest -> A-tile L2 reuse
    const int mTile = blockIdx.y;

    if (tid < 128) {
        int m   = mTile * 128 + tid;
        int win = m >> 6, t = m & 63;
        int b   = win >> 8;
        int wh  = (win >> 4) & 15;
        int ww  = win & 15;
        int i   = t >> 3, j = t & 7;
        int r   = (wh * 8 + i + 4) & 127;     // roll(-4) gather
        int c   = (ww * 8 + j + 4) & 127;
        rowOff[tid] = ((((b << 7) | r) << 7) | c) << 9;   // *512 elements
    }
    __syncthreads();

    const int warpId = tid >> 5, lane = tid & 31;
    const int warpM  = warpId & 3;
    const int warpN  = warpId >> 2;
    const int n0     = nTile * 128;
    const int r      = lane >> 2, cq = lane & 3;

    float acc[2][8][4];
#pragma unroll
    for (int mi = 0; mi < 2; mi++)
#pragma unroll
        for (int ni = 0; ni < 8; ni++)
#pragma unroll
            for (int e = 0; e < 4; e++) acc[mi][ni][e] = 0.f;

    auto loadStage = [&](int s, int k0) {
        float* As = sm + s * STAGE_F;
        float* Bs = As + 128 * SSTRIDE;
#pragma unroll
        for (int it = 0; it < 4; it++) {
            int ch = tid + it * 256;
            int row = ch >> 3, ci = ch & 7;
            uint32_t sa = (uint32_t)__cvta_generic_to_shared(As + row * SSTRIDE + ci * 4);
            cp16(sa, x + rowOff[row] + k0 + ci * 4);
            uint32_t sb = (uint32_t)__cvta_generic_to_shared(Bs + row * SSTRIDE + ci * 4);
            cp16(sb, g_wq + (size_t)(n0 + row) * 512 + k0 + ci * 4);
        }
    };

    loadStage(0, 0);
    asm volatile("cp.async.commit_group;\n");
    loadStage(1, 32);
    asm volatile("cp.async.commit_group;\n");
    asm volatile("cp.async.wait_group 1;\n");   // stage 0 ready
    __syncthreads();

    int ldS = 2;   // stage to load next
    int cpS = 0;   // stage to compute

    for (int kt = 0; kt < 16; kt++) {
        if (kt + 2 < 16) {
            loadStage(ldS, (kt + 2) * 32);
            asm volatile("cp.async.commit_group;\n");
            if (++ldS == 3) ldS = 0;
        }

        const float*    As = sm + cpS * STAGE_F;
        const uint32_t* Bs = (const uint32_t*)(As + 128 * SSTRIDE);
#pragma unroll
        for (int ks = 0; ks < 4; ks++) {
            uint32_t af[2][4];
#pragma unroll
            for (int mi = 0; mi < 2; mi++) {
                const float* ap = As + (warpM * 32 + mi * 16 + r) * SSTRIDE + ks * 8 + cq;
                af[mi][0] = f2tf32(ap[0]);
                af[mi][1] = f2tf32(ap[8 * SSTRIDE]);
                af[mi][2] = f2tf32(ap[4]);
                af[mi][3] = f2tf32(ap[8 * SSTRIDE + 4]);
            }
#pragma unroll
            for (int ni = 0; ni < 8; ni++) {
                const uint32_t* bp = Bs + (warpN * 64 + ni * 8 + r) * SSTRIDE + ks * 8 + cq;
                uint32_t bf[2] = { bp[0], bp[4] };
                mma_tf32(acc[0][ni], af[0], bf);
                mma_tf32(acc[1][ni], af[1], bf);
            }
        }
        if (++cpS == 3) cpS = 0;

        if (kt < 15) {
            if (kt + 2 < 16) asm volatile("cp.async.wait_group 1;\n");
            else             asm volatile("cp.async.wait_group 0;\n");
            __syncthreads();
        }
    }

    // Epilogue: bias + scatter into g_qkv[part][win][h][t][d]
#pragma unroll
    for (int ni = 0; ni < 8; ni++) {
        int n  = n0 + warpN * 64 + ni * 8 + 2 * cq;
        float b0 = bias[n], b1 = bias[n + 1];
        int part = n >> 9;
        int h    = (n >> 6) & 7;
        int d0   = n & 63;
#pragma unroll
        for (int mi = 0; mi < 2; mi++) {
#pragma unroll
            for (int rr = 0; rr < 2; rr++) {
                int m   = mTile * 128 + warpM * 32 + mi * 16 + r + rr * 8;
                int win = m >> 6, t = m & 63;
                size_t idx = ((((size_t)part * 2048 + win) * 8 + h) * 64 + t) * 64 + d0;
                float2 v = make_float2(acc[mi][ni][rr * 2 + 0] + b0,
                                       acc[mi][ni][rr * 2 + 1] + b1);
                *(float2*)(g_qkv + idx) = v;
            }
        }
    }
}

// ---------------------------------------------------------------------------
// Kernel 2: per (window, head) attention on tensor cores (tf32 mma.sync).
// Writes tf32-rounded O to g_o so proj consumes it without cvts.
// ---------------------------------------------------------------------------
#define AST 68

__global__ __launch_bounds__(128) void k_attn_mma()
{
    __shared__ float Qb[64 * AST];
    __shared__ float Kb[64 * AST];

    const int tid  = threadIdx.x;
    const int warp = tid >> 5;
    const int lane = tid & 31;
    const int r    = lane >> 2;
    const int c    = lane & 3;
    const int m0   = warp * 16;

    const int win = blockIdx.x >> 3;
    const int h   = blockIdx.x & 7;

    const size_t qbase = ((size_t)win * 8 + h) * 4096;
    const float4* qg = (const float4*)(g_qkv + qbase);
    const float4* kg = (const float4*)(g_qkv + (size_t)2048 * 8 * 4096 + qbase);
    const float4* vg = (const float4*)(g_qkv + (size_t)2 * 2048 * 8 * 4096 + qbase);

#pragma unroll
    for (int it = 0; it < 8; it++) {
        int e4 = tid + it * 128;
        int t  = e4 >> 4;
        int d4 = (e4 & 15) * 4;
        *(float4*)(Qb + t * AST + d4) = qg[e4];
        *(float4*)(Kb + t * AST + d4) = kg[e4];
    }
    __syncthreads();

    const float L2_10000 = 13.287712379549449f;
#pragma unroll
    for (int it = 0; it < 16; it++) {
        int p = tid + it * 128;
        int t = p >> 5, q = p & 31;
        int db = (q < 16) ? q : (q + 16);
        int e  = db & 15;
        float pos = (db < 32) ? (float)(t >> 3) : (float)(t & 7);
        float inv = exp2f(-(float)e * (L2_10000 / 16.f));
        float ang = pos * inv;
        float cv = cosf(ang), sv = sinf(ang);

        float a = Qb[t * AST + db], b = Qb[t * AST + db + 16];
        Qb[t * AST + db]      = (a * cv - b * sv) * 0.125f;
        Qb[t * AST + db + 16] = (b * cv + a * sv) * 0.125f;

        a = Kb[t * AST + db]; b = Kb[t * AST + db + 16];
        Kb[t * AST + db]      = a * cv - b * sv;
        Kb[t * AST + db + 16] = b * cv + a * sv;
    }
    __syncthreads();

    uint32_t areg[8][4];
#pragma unroll
    for (int ks = 0; ks < 8; ks++) {
        const float* ap = Qb + (m0 + r) * AST + ks * 8 + c;
        areg[ks][0] = f2tf32(ap[0]);
        areg[ks][1] = f2tf32(ap[8 * AST]);
        areg[ks][2] = f2tf32(ap[4]);
        areg[ks][3] = f2tf32(ap[8 * AST + 4]);
    }

    float sacc[8][4];
#pragma unroll
    for (int ni = 0; ni < 8; ni++)
#pragma unroll
        for (int e = 0; e < 4; e++) sacc[ni][e] = 0.f;

#pragma unroll
    for (int ni = 0; ni < 8; ni++) {
        const float* bbase = Kb + (ni * 8 + r) * AST + c;
#pragma unroll
        for (int ks = 0; ks < 8; ks++) {
            uint32_t bf[2];
            bf[0] = f2tf32(bbase[ks * 8]);
            bf[1] = f2tf32(bbase[ks * 8 + 4]);
            mma_tf32(sacc[ni], areg[ks], bf);
        }
    }
    __syncthreads();

#pragma unroll
    for (int it = 0; it < 8; it++) {
        int e4 = tid + it * 128;
        int t  = e4 >> 4;
        int d4 = (e4 & 15) * 4;
        *(float4*)(Kb + t * AST + d4) = vg[e4];
    }

    const bool maskOn = (((win >> 4) & 15) == 15);
    const bool warpLo = (warp < 2);

    float mx1 = -1e30f, mx2 = -1e30f;
#pragma unroll
    for (int ni = 0; ni < 8; ni++) {
        float msub = (maskOn && ((ni < 4) != warpLo)) ? 100.f : 0.f;
        sacc[ni][0] -= msub; sacc[ni][1] -= msub;
        sacc[ni][2] -= msub; sacc[ni][3] -= msub;
        mx1 = fmaxf(mx1, fmaxf(sacc[ni][0], sacc[ni][1]));
        mx2 = fmaxf(mx2, fmaxf(sacc[ni][2], sacc[ni][3]));
    }
    mx1 = fmaxf(mx1, __shfl_xor_sync(0xffffffffu, mx1, 1));
    mx1 = fmaxf(mx1, __shfl_xor_sync(0xffffffffu, mx1, 2));
    mx2 = fmaxf(mx2, __shfl_xor_sync(0xffffffffu, mx2, 1));
    mx2 = fmaxf(mx2, __shfl_xor_sync(0xffffffffu, mx2, 2));

    float s1 = 0.f, s2 = 0.f;
#pragma unroll
    for (int ni = 0; ni < 8; ni++) {
        sacc[ni][0] = __expf(sacc[ni][0] - mx1);
        sacc[ni][1] = __expf(sacc[ni][1] - mx1);
        sacc[ni][2] = __expf(sacc[ni][2] - mx2);
        sacc[ni][3] = __expf(sacc[ni][3] - mx2);
        s1 += sacc[ni][0] + sacc[ni][1];
        s2 += sacc[ni][2] + sacc[ni][3];
    }
    s1 += __shfl_xor_sync(0xffffffffu, s1, 1);
    s1 += __shfl_xor_sync(0xffffffffu, s1, 2);
    s2 += __shfl_xor_sync(0xffffffffu, s2, 1);
    s2 += __shfl_xor_sync(0xffffffffu, s2, 2);
    const float i1 = 1.f / s1, i2 = 1.f / s2;

#pragma unroll
    for (int ni = 0; ni < 8; ni++) {
        *(float2*)(Qb + (m0 + r) * AST + ni * 8 + 2 * c) =
            make_float2(sacc[ni][0] * i1, sacc[ni][1] * i1);
        *(float2*)(Qb + (m0 + r + 8) * AST + ni * 8 + 2 * c) =
            make_float2(sacc[ni][2] * i2, sacc[ni][3] * i2);
    }
    __syncthreads();

    uint32_t preg[8][4];
#pragma unroll
    for (int ks = 0; ks < 8; ks++) {
        const float* pp = Qb + (m0 + r) * AST + ks * 8 + c;
        preg[ks][0] = f2tf32(pp[0]);
        preg[ks][1] = f2tf32(pp[8 * AST]);
        preg[ks][2] = f2tf32(pp[4]);
        preg[ks][3] = f2tf32(pp[8 * AST + 4]);
    }

    float oacc[8][4];
#pragma unroll
    for (int ni = 0; ni < 8; ni++)
#pragma unroll
        for (int e = 0; e < 4; e++) oacc[ni][e] = 0.f;

#pragma unroll
    for (int ni = 0; ni < 8; ni++) {
        const float* vb = Kb + c * AST + ni * 8 + r;
#pragma unroll
        for (int ks = 0; ks < 8; ks++) {
            uint32_t bf[2];
            bf[0] = f2tf32(vb[ks * 8 * AST]);
            bf[1] = f2tf32(vb[(ks * 8 + 4) * AST]);
            mma_tf32(oacc[ni], preg[ks], bf);
        }
    }

    uint32_t* go32 = (uint32_t*)g_o;
    const size_t mrow1 = (size_t)win * 64 + m0 + r;
    const size_t mrow2 = mrow1 + 8;
#pragma unroll
    for (int ni = 0; ni < 8; ni++) {
        int d0 = h * 64 + ni * 8 + 2 * c;
        uint2 v1 = make_uint2(f2tf32(oacc[ni][0]), f2tf32(oacc[ni][1]));
        uint2 v2 = make_uint2(f2tf32(oacc[ni][2]), f2tf32(oacc[ni][3]));
        *(uint2*)(go32 + mrow1 * 512 + d0) = v1;
        *(uint2*)(go32 + mrow2 * 512 + d0) = v2;
    }
}

// ---------------------------------------------------------------------------
// Kernel 3: proj GEMM (tf32, pre-rounded) + bias + unpartition/roll scatter.
// Same 3-stage / 1-barrier pipeline.
// ---------------------------------------------------------------------------
__global__ __launch_bounds__(256, 2) void k_proj_gemm(const float* __restrict__ bias,
                                                      float* __restrict__ out)
{
    extern __shared__ float sm[];

    const int tid   = threadIdx.x;
    const int nTile = blockIdx.x;
    const int mTile = blockIdx.y;

    const int warpId = tid >> 5, lane = tid & 31;
    const int warpM  = warpId & 3;
    const int warpN  = warpId >> 2;
    const int n0     = nTile * 128;
    const int r      = lane >> 2, cq = lane & 3;

    float acc[2][8][4];
#pragma unroll
    for (int mi = 0; mi < 2; mi++)
#pragma unroll
        for (int ni = 0; ni < 8; ni++)
#pragma unroll
            for (int e = 0; e < 4; e++) acc[mi][ni][e] = 0.f;

    auto loadStage = [&](int s, int k0) {
        float* As = sm + s * STAGE_F;
        float* Bs = As + 128 * SSTRIDE;
#pragma unroll
        for (int it = 0; it < 4; it++) {
            int ch = tid + it * 256;
            int row = ch >> 3, ci = ch & 7;
            uint32_t sa = (uint32_t)__cvta_generic_to_shared(As + row * SSTRIDE + ci * 4);
            cp16(sa, g_o + (size_t)(mTile * 128 + row) * 512 + k0 + ci * 4);
            uint32_t sb = (uint32_t)__cvta_generic_to_shared(Bs + row * SSTRIDE + ci * 4);
            cp16(sb, g_wp + (size_t)(n0 + row) * 512 + k0 + ci * 4);
        }
    };

    loadStage(0, 0);
    asm volatile("cp.async.commit_group;\n");
    loadStage(1, 32);
    asm volatile("cp.async.commit_group;\n");
    asm volatile("cp.async.wait_group 1;\n");
    __syncthreads();

    int ldS = 2;
    int cpS = 0;

    for (int kt = 0; kt < 16; kt++) {
        if (kt + 2 < 16) {
            loadStage(ldS, (kt + 2) * 32);
            asm volatile("cp.async.commit_group;\n");
            if (++ldS == 3) ldS = 0;
        }

        const uint32_t* As = (const uint32_t*)(sm + cpS * STAGE_F);
        const uint32_t* Bs = As + 128 * SSTRIDE;
#pragma unroll
        for (int ks = 0; ks < 4; ks++) {
            uint32_t af[2][4];
#pragma unroll
            for (int mi = 0; mi < 2; mi++) {
                const uint32_t* ap = As + (warpM * 32 + mi * 16 + r) * SSTRIDE + ks * 8 + cq;
                af[mi][0] = ap[0];
                af[mi][1] = ap[8 * SSTRIDE];
                af[mi][2] = ap[4];
                af[mi][3] = ap[8 * SSTRIDE + 4];
            }
#pragma unroll
            for (int ni = 0; ni < 8; ni++) {
                const uint32_t* bp = Bs + (warpN * 64 + ni * 8 + r) * SSTRIDE + ks * 8 + cq;
                uint32_t bf[2] = { bp[0], bp[4] };
                mma_tf32(acc[0][ni], af[0], bf);
                mma_tf32(acc[1][ni], af[1], bf);
            }
        }
        if (++cpS == 3) cpS = 0;

        if (kt < 15) {
            if (kt + 2 < 16) asm volatile("cp.async.wait_group 1;\n");
            else             asm volatile("cp.async.wait_group 0;\n");
            __syncthreads();
        }
    }

#pragma unroll
    for (int ni = 0; ni < 8; ni++) {
        int n  = n0 + warpN * 64 + ni * 8 + 2 * cq;
        float b0 = bias[n], b1 = bias[n + 1];
#pragma unroll
        for (int mi = 0; mi < 2; mi++) {
#pragma unroll
            for (int rr2 = 0; rr2 < 2; rr2++) {
                int m   = mTile * 128 + warpM * 32 + mi * 16 + r + rr2 * 8;
                int win = m >> 6, t = m & 63;
                int b   = win >> 8;
                int wh  = (win >> 4) & 15;
                int ww  = win & 15;
                int ii  = t >> 3, jj = t & 7;
                int rO  = (wh * 8 + ii + 4) & 127;
                int cO  = (ww * 8 + jj + 4) & 127;
                size_t off = ((((size_t)b << 7) | rO) << 7 | cO) << 9;
                float2 v = make_float2(acc[mi][ni][rr2 * 2 + 0] + b0,
                                       acc[mi][ni][rr2 * 2 + 1] + b1);
                *(float2*)(out + off + n) = v;
            }
        }
    }
}

// ---------------------------------------------------------------------------
extern "C" void kernel_launch(void* const* d_in, const int* in_sizes, int n_in,
                              void* d_out, int out_size)
{
    const float* x      = (const float*)d_in[0];
    const float* qkv_w  = (const float*)d_in[1];
    const float* qkv_b  = (const float*)d_in[2];
    const float* proj_w = (const float*)d_in[3];
    const float* proj_b = (const float*)d_in[4];
    float* out = (float*)d_out;

    cudaFuncSetAttribute(k_qkv_gemm,  cudaFuncAttributeMaxDynamicSharedMemorySize, SMEM_BYTES);
    cudaFuncSetAttribute(k_proj_gemm, cudaFuncAttributeMaxDynamicSharedMemorySize, SMEM_BYTES);

    k_prep_w<<<2048, 128>>>(qkv_w, proj_w);
    k_qkv_gemm<<<dim3(12, 1024), 256, SMEM_BYTES>>>(x, qkv_b);
    k_attn_mma<<<2048 * 8, 128>>>();
    k_proj_gemm<<<dim3(4, 1024), 256, SMEM_BYTES>>>(proj_b, out);
}